// round 10
// baseline (speedup 1.0000x reference)
#include <cuda_runtime.h>
#include <math.h>
#include <stdint.h>

#define SS 4096
#define HH 1280
#define NHEAD 16
#define HDIM 80
#define IDIM 5120
#define EPSV 1e-6f

// ---------------- scratch (static device memory; no allocs allowed) --------
__device__ float g_ln  [(size_t)SS * HH];
__device__ float g_qkv [(size_t)SS * 3 * HH];
__device__ float g_ctx [(size_t)SS * HH];
__device__ float g_x1  [(size_t)SS * HH];
__device__ float g_ffn [(size_t)SS * IDIM];
// tf32-rounded weight copies
__device__ float g_wqkv[(size_t)3 * HH * HH];
__device__ float g_wproj[(size_t)HH * HH];
__device__ float g_wfc1[(size_t)IDIM * HH];
__device__ float g_wfc2[(size_t)HH * IDIM];

// ---------------- helpers ---------------------------------------------------
__device__ __forceinline__ float to_tf32(float x) {
    float r;
    asm("cvt.rna.tf32.f32 %0, %1;" : "=f"(r) : "f"(x));
    return r;
}
__device__ __forceinline__ float4 cvt4(float4 v) {
    v.x = to_tf32(v.x); v.y = to_tf32(v.y); v.z = to_tf32(v.z); v.w = to_tf32(v.w);
    return v;
}
__device__ __forceinline__ uint32_t smem_u32(const void* p) {
    uint32_t a;
    asm("{ .reg .u64 t; cvta.to.shared.u64 t, %1; cvt.u32.u64 %0, t; }" : "=r"(a) : "l"(p));
    return a;
}
__device__ __forceinline__ void mma_tf32(float* d, uint32_t a0, uint32_t a1,
                                         uint32_t a2, uint32_t a3,
                                         uint32_t b0, uint32_t b1) {
    asm volatile(
        "mma.sync.aligned.m16n8k8.row.col.f32.tf32.tf32.f32 "
        "{%0,%1,%2,%3}, {%4,%5,%6,%7}, {%8,%9}, {%0,%1,%2,%3};"
        : "+f"(d[0]), "+f"(d[1]), "+f"(d[2]), "+f"(d[3])
        : "r"(a0), "r"(a1), "r"(a2), "r"(a3), "r"(b0), "r"(b1));
}
#define CP_ASYNC16(dst, src) \
    asm volatile("cp.async.cg.shared.global [%0], [%1], 16;" :: "r"(dst), "l"(src) : "memory")
#define CP_COMMIT() asm volatile("cp.async.commit_group;" ::: "memory")
#define CP_WAIT(n)  asm volatile("cp.async.wait_group %0;" :: "n"(n) : "memory")

// ---------------- weight rounding (all four in one launch) ------------------
__global__ void round_all_kernel(const float* s0, float* d0, int n0,
                                 const float* s1, float* d1, int n1,
                                 const float* s2, float* d2, int n2,
                                 const float* s3, float* d3, int n3) {
    const float* src; float* dst; int n;
    switch (blockIdx.y) {
        case 0: src = s0; dst = d0; n = n0; break;
        case 1: src = s1; dst = d1; n = n1; break;
        case 2: src = s2; dst = d2; n = n2; break;
        default: src = s3; dst = d3; n = n3; break;
    }
    int i = blockIdx.x * blockDim.x + threadIdx.x;
    if (i < n) ((float4*)dst)[i] = cvt4(((const float4*)src)[i]);
}

// ---------------- reductions ----------------------------------------------
__device__ __forceinline__ float block_reduce_sum(float v) {
    __shared__ float sh_sum[32];
    int lane = threadIdx.x & 31, wid = threadIdx.x >> 5;
    #pragma unroll
    for (int o = 16; o; o >>= 1) v += __shfl_xor_sync(0xffffffffu, v, o);
    if (lane == 0) sh_sum[wid] = v;
    __syncthreads();
    v = (threadIdx.x < (blockDim.x >> 5)) ? sh_sum[threadIdx.x] : 0.f;
    if (wid == 0) {
        #pragma unroll
        for (int o = 16; o; o >>= 1) v += __shfl_xor_sync(0xffffffffu, v, o);
        if (lane == 0) sh_sum[0] = v;
    }
    __syncthreads();
    float r = sh_sum[0];
    __syncthreads();
    return r;
}

// ---------------- layernorm (tf32-rounded output) ---------------------------
__global__ void ln_kernel(const float* __restrict__ x, const float* __restrict__ g,
                          const float* __restrict__ b, float* __restrict__ out) {
    int row = blockIdx.x;
    const float* xr = x + (size_t)row * HH;
    float v[5]; float s = 0.f;
    #pragma unroll
    for (int i = 0; i < 5; i++) { v[i] = xr[threadIdx.x + i * 256]; s += v[i]; }
    float mean = block_reduce_sum(s) * (1.f / HH);
    float vs = 0.f;
    #pragma unroll
    for (int i = 0; i < 5; i++) { float d = v[i] - mean; vs += d * d; }
    float var = block_reduce_sum(vs) * (1.f / HH);
    float inv = rsqrtf(var + EPSV);
    float* o = out + (size_t)row * HH;
    #pragma unroll
    for (int i = 0; i < 5; i++) {
        int c = threadIdx.x + i * 256;
        o[c] = to_tf32((v[i] - mean) * inv * g[c] + b[c]);
    }
}

// ---------------- RoPE (tf32-rounded output) --------------------------------
__global__ void rope_kernel(float* __restrict__ qkv, const float* __restrict__ cs,
                            const float* __restrict__ sn) {
    int idx = blockIdx.x * blockDim.x + threadIdx.x;
    if (idx >= SS * NHEAD * (HDIM / 2)) return;
    int d = idx % (HDIM / 2);
    int h = (idx / (HDIM / 2)) % NHEAD;
    int s = idx / ((HDIM / 2) * NHEAD);
    float c1 = cs[s * HDIM + d], c2 = cs[s * HDIM + d + 40];
    float s1 = sn[s * HDIM + d], s2 = sn[s * HDIM + d + 40];
    size_t base = (size_t)s * 3 * HH + h * HDIM;
    float* qp = qkv + base;
    float a = qp[d], bb = qp[d + 40];
    qp[d]      = to_tf32(a * c1 - bb * s1);
    qp[d + 40] = to_tf32(bb * c2 + a * s2);
    float* kp = qkv + base + HH;
    a = kp[d]; bb = kp[d + 40];
    kp[d]      = to_tf32(a * c1 - bb * s1);
    kp[d + 40] = to_tf32(bb * c2 + a * s2);
}

__device__ __forceinline__ float gelu_tanh(float x) {
    return 0.5f * x * (1.f + tanhf(0.7978845608028654f * (x + 0.044715f * x * x * x)));
}

// ================= flash attention v2 (cp.async double-buffered) ============
#define KSP 84
#define VSP 88
#define KS_STRIDE (128 * KSP)   // 10752
#define VS_STRIDE (128 * VSP)   // 11264
__global__ void __launch_bounds__(256)
flash_kernel(const float* __restrict__ qkv, const float* __restrict__ mask,
             float* __restrict__ ctx) {
    extern __shared__ float fsm[];
    float* Ks = fsm;                         // 2 x KS_STRIDE
    float* Vs = fsm + 2 * KS_STRIDE;         // 2 x VS_STRIDE
    float* Qstage = Vs + VS_STRIDE;          // aliases Vs buf1 (prologue only)
    const uint32_t smb = smem_u32(fsm);

    const int tid  = threadIdx.x;
    const int wid  = tid >> 5;
    const int lane = tid & 31;
    const int g4   = lane >> 2;
    const int kl   = lane & 3;
    const int bm   = blockIdx.x * 128;
    const int h    = blockIdx.y;
    const float scale = rsqrtf((float)HDIM);

    const float* Qb = qkv + h * HDIM;
    const float* Kb = qkv + HH + h * HDIM;
    const float* Vb = qkv + 2 * HH + h * HDIM;

    auto issue = [&](int kv0, int b) {
        uint32_t kbase = smb + (uint32_t)(b * KS_STRIDE) * 4;
        uint32_t vbase = smb + (uint32_t)((2 * KS_STRIDE) + b * VS_STRIDE) * 4;
        #pragma unroll
        for (int i = 0; i < 10; i++) {
            int c = i * 256 + tid;
            int row = c / 20, col = (c % 20) * 4;
            CP_ASYNC16(kbase + (uint32_t)(row * KSP + col) * 4,
                       Kb + (size_t)(kv0 + row) * (3 * HH) + col);
            CP_ASYNC16(vbase + (uint32_t)(row * VSP + col) * 4,
                       Vb + (size_t)(kv0 + row) * (3 * HH) + col);
        }
        CP_COMMIT();
    };

    issue(0, 0);

    {
        const int lr = tid >> 1;
        const int lc = (tid & 1) * 40;
        const float* src = Qb + (size_t)(bm + lr) * (3 * HH) + lc;
        float* dst = Qstage + lr * KSP + lc;
        #pragma unroll
        for (int i = 0; i < 10; i++)
            *(float4*)(dst + i * 4) = *(const float4*)(src + i * 4);
    }
    __syncthreads();
    uint32_t qa[10][4];
    {
        int r0 = wid * 16 + g4;
        #pragma unroll
        for (int ks = 0; ks < 10; ks++) {
            qa[ks][0] = __float_as_uint(Qstage[r0 * KSP + ks * 8 + kl]);
            qa[ks][1] = __float_as_uint(Qstage[(r0 + 8) * KSP + ks * 8 + kl]);
            qa[ks][2] = __float_as_uint(Qstage[r0 * KSP + ks * 8 + kl + 4]);
            qa[ks][3] = __float_as_uint(Qstage[(r0 + 8) * KSP + ks * 8 + kl + 4]);
        }
    }

    float Oa[10][4];
    #pragma unroll
    for (int i = 0; i < 10; i++)
        #pragma unroll
        for (int j = 0; j < 4; j++) Oa[i][j] = 0.f;
    float m0 = -INFINITY, m1 = -INFINITY, l0 = 0.f, l1 = 0.f;

    const float* mrow0 = mask + (size_t)(bm + wid * 16 + g4) * SS;
    const float* mrow1 = mrow0 + (size_t)8 * SS;

    const int src_lo = (lane & ~3) | (kl >> 1);
    const int src_hi = src_lo + 2;

    constexpr int NT = SS / 128;
    for (int s = 0; s < NT; s++) {
        const int buf = s & 1;
        const int kv0 = s * 128;
        __syncthreads();
        if (s + 1 < NT) issue((s + 1) * 128, buf ^ 1);
        if (s + 1 < NT) { CP_WAIT(1); } else { CP_WAIT(0); }
        __syncthreads();

        const float* K_ = Ks + buf * KS_STRIDE;
        const float* V_ = Vs + buf * VS_STRIDE;

        float sa[16][4];
        #pragma unroll
        for (int nt = 0; nt < 16; nt++)
            #pragma unroll
            for (int j = 0; j < 4; j++) sa[nt][j] = 0.f;
        #pragma unroll
        for (int ks = 0; ks < 10; ks++) {
            #pragma unroll
            for (int nt = 0; nt < 16; nt++) {
                uint32_t b0 = __float_as_uint(K_[(nt * 8 + g4) * KSP + ks * 8 + kl]);
                uint32_t b1 = __float_as_uint(K_[(nt * 8 + g4) * KSP + ks * 8 + kl + 4]);
                mma_tf32(sa[nt], qa[ks][0], qa[ks][1], qa[ks][2], qa[ks][3], b0, b1);
            }
        }

        float tmx0 = -INFINITY, tmx1 = -INFINITY;
        #pragma unroll
        for (int nt = 0; nt < 16; nt++) {
            float2 mk0 = *(const float2*)(mrow0 + kv0 + nt * 8 + 2 * kl);
            float2 mk1 = *(const float2*)(mrow1 + kv0 + nt * 8 + 2 * kl);
            sa[nt][0] = sa[nt][0] * scale + mk0.x;
            sa[nt][1] = sa[nt][1] * scale + mk0.y;
            sa[nt][2] = sa[nt][2] * scale + mk1.x;
            sa[nt][3] = sa[nt][3] * scale + mk1.y;
            tmx0 = fmaxf(tmx0, fmaxf(sa[nt][0], sa[nt][1]));
            tmx1 = fmaxf(tmx1, fmaxf(sa[nt][2], sa[nt][3]));
        }
        tmx0 = fmaxf(tmx0, __shfl_xor_sync(0xffffffffu, tmx0, 1));
        tmx0 = fmaxf(tmx0, __shfl_xor_sync(0xffffffffu, tmx0, 2));
        tmx1 = fmaxf(tmx1, __shfl_xor_sync(0xffffffffu, tmx1, 1));
        tmx1 = fmaxf(tmx1, __shfl_xor_sync(0xffffffffu, tmx1, 2));

        float nm0 = fmaxf(m0, tmx0), nm1 = fmaxf(m1, tmx1);
        float f0 = __expf(m0 - nm0), f1 = __expf(m1 - nm1);
        m0 = nm0; m1 = nm1;

        float ts0 = 0.f, ts1 = 0.f;
        #pragma unroll
        for (int nt = 0; nt < 16; nt++) {
            sa[nt][0] = __expf(sa[nt][0] - nm0);
            sa[nt][1] = __expf(sa[nt][1] - nm0);
            sa[nt][2] = __expf(sa[nt][2] - nm1);
            sa[nt][3] = __expf(sa[nt][3] - nm1);
            ts0 += sa[nt][0] + sa[nt][1];
            ts1 += sa[nt][2] + sa[nt][3];
        }
        ts0 += __shfl_xor_sync(0xffffffffu, ts0, 1);
        ts0 += __shfl_xor_sync(0xffffffffu, ts0, 2);
        ts1 += __shfl_xor_sync(0xffffffffu, ts1, 1);
        ts1 += __shfl_xor_sync(0xffffffffu, ts1, 2);
        l0 = l0 * f0 + ts0;
        l1 = l1 * f1 + ts1;

        #pragma unroll
        for (int no = 0; no < 10; no++) {
            Oa[no][0] *= f0; Oa[no][1] *= f0;
            Oa[no][2] *= f1; Oa[no][3] *= f1;
        }

        #pragma unroll
        for (int nt = 0; nt < 16; nt++) {
            float p0 = to_tf32(sa[nt][0]), p1 = to_tf32(sa[nt][1]);
            float p2 = to_tf32(sa[nt][2]), p3 = to_tf32(sa[nt][3]);
            float a0l = __shfl_sync(0xffffffffu, p0, src_lo);
            float a0h = __shfl_sync(0xffffffffu, p1, src_lo);
            float a1l = __shfl_sync(0xffffffffu, p2, src_lo);
            float a1h = __shfl_sync(0xffffffffu, p3, src_lo);
            float a2l = __shfl_sync(0xffffffffu, p0, src_hi);
            float a2h = __shfl_sync(0xffffffffu, p1, src_hi);
            float a3l = __shfl_sync(0xffffffffu, p2, src_hi);
            float a3h = __shfl_sync(0xffffffffu, p3, src_hi);
            bool odd = (kl & 1);
            uint32_t A0 = __float_as_uint(odd ? a0h : a0l);
            uint32_t A1 = __float_as_uint(odd ? a1h : a1l);
            uint32_t A2 = __float_as_uint(odd ? a2h : a2l);
            uint32_t A3 = __float_as_uint(odd ? a3h : a3l);
            #pragma unroll
            for (int no = 0; no < 10; no++) {
                uint32_t b0 = __float_as_uint(V_[(nt * 8 + kl) * VSP + no * 8 + g4]);
                uint32_t b1 = __float_as_uint(V_[(nt * 8 + kl + 4) * VSP + no * 8 + g4]);
                mma_tf32(Oa[no], A0, A1, A2, A3, b0, b1);
            }
        }
    }

    float i0 = 1.f / l0, i1 = 1.f / l1;
    int r0 = bm + wid * 16 + g4;
    float* c0p = ctx + (size_t)r0 * HH + h * HDIM;
    float* c1p = c0p + (size_t)8 * HH;
    #pragma unroll
    for (int no = 0; no < 10; no++) {
        *(float2*)(c0p + no * 8 + 2 * kl) =
            make_float2(to_tf32(Oa[no][0] * i0), to_tf32(Oa[no][1] * i0));
        *(float2*)(c1p + no * 8 + 2 * kl) =
            make_float2(to_tf32(Oa[no][2] * i1), to_tf32(Oa[no][3] * i1));
    }
}

// ================= TF32 GEMM v4: cp.async 2-stage, 3 CTAs/SM ================
// Inputs pre-rounded to tf32 -> HW truncation is exact.
// CTA 128x128x32, 128 threads = 4 warps (2m x 2n), warp tile 64x64.
// 2 stages x 32KB = 64KB smem -> 3 CTAs/SM (12 warps/SM vs 8 at 3-stage).
template<int ACT, int OUTR>
__global__ void __launch_bounds__(128, 3)
mma_gemm(const float* __restrict__ A, int lda,
         const float* __restrict__ B, int ldb,
         float* __restrict__ C, int ldc,
         const float* __restrict__ bias,
         const float* __restrict__ Rsd, int ldr,
         int N, int K) {
    extern __shared__ float sm[];           // 2 stages x 8192 floats
    const uint32_t smb = smem_u32(sm);

    const int tid = threadIdx.x;
    const int wid = tid >> 5;
    const int lane = tid & 31;
    const int g4 = lane >> 2;
    const int kl = lane & 3;
    const int warpM = (wid >> 1) * 64;
    const int warpN = (wid & 1) * 64;
    const int bm = blockIdx.y * 128;
    const int bn = blockIdx.x * 128;

    float acc[4][8][4];
    #pragma unroll
    for (int i = 0; i < 4; i++)
        #pragma unroll
        for (int j = 0; j < 8; j++)
            #pragma unroll
            for (int q = 0; q < 4; q++) acc[i][j][q] = 0.f;

    auto issue = [&](int k0, int st) {
        uint32_t ab = smb + st * 32768;
        uint32_t bb = ab + 16384;
        #pragma unroll
        for (int i = 0; i < 8; i++) {
            int idx = i * 128 + tid;
            int row = idx >> 3, col = idx & 7;
            uint32_t sw = (uint32_t)((col ^ (row & 7)) << 4);
            CP_ASYNC16(ab + row * 128 + sw, A + (size_t)(bm + row) * lda + k0 + col * 4);
            CP_ASYNC16(bb + row * 128 + sw, B + (size_t)(bn + row) * ldb + k0 + col * 4);
        }
        CP_COMMIT();
    };

    auto compute = [&](int st) {
        const float* As = sm + st * 8192;
        const float* Bs = As + 4096;
        #pragma unroll
        for (int ko = 0; ko < 4; ko++) {
            const int cc0 = (((ko * 2)     ^ g4) << 2) | kl;
            const int cc1 = (((ko * 2 + 1) ^ g4) << 2) | kl;
            uint32_t af[4][4], bf[8][2];
            #pragma unroll
            for (int mt = 0; mt < 4; mt++) {
                int m = warpM + mt * 16 + g4;
                af[mt][0] = __float_as_uint(As[m * 32 + cc0]);
                af[mt][1] = __float_as_uint(As[(m + 8) * 32 + cc0]);
                af[mt][2] = __float_as_uint(As[m * 32 + cc1]);
                af[mt][3] = __float_as_uint(As[(m + 8) * 32 + cc1]);
            }
            #pragma unroll
            for (int nt = 0; nt < 8; nt++) {
                int n = warpN + nt * 8 + g4;
                bf[nt][0] = __float_as_uint(Bs[n * 32 + cc0]);
                bf[nt][1] = __float_as_uint(Bs[n * 32 + cc1]);
            }
            #pragma unroll
            for (int mt = 0; mt < 4; mt++)
                #pragma unroll
                for (int nt = 0; nt < 8; nt++)
                    mma_tf32(acc[mt][nt], af[mt][0], af[mt][1], af[mt][2], af[mt][3],
                             bf[nt][0], bf[nt][1]);
        }
    };

    const int nst = K / 32;
    issue(0, 0);
    for (int s = 0; s < nst; s++) {
        const int buf = s & 1;
        if (s + 1 < nst) { issue((s + 1) * 32, buf ^ 1); CP_WAIT(1); }
        else             { CP_WAIT(0); }
        __syncthreads();
        compute(buf);
        __syncthreads();   // before next issue overwrites buf
    }

    // ---- epilogue ----
    #pragma unroll
    for (int mt = 0; mt < 4; mt++) {
        #pragma unroll
        for (int rr = 0; rr < 2; rr++) {
            int r_ = bm + warpM + mt * 16 + g4 + rr * 8;
            float* Crow = C + (size_t)r_ * ldc;
            const float* Rrow = Rsd ? (Rsd + (size_t)r_ * ldr) : nullptr;
            #pragma unroll
            for (int nt = 0; nt < 8; nt++) {
                int col = bn + warpN + nt * 8 + kl * 2;
                float v0 = acc[mt][nt][rr * 2 + 0];
                float v1 = acc[mt][nt][rr * 2 + 1];
                if (bias) { v0 += bias[col]; v1 += bias[col + 1]; }
                if (ACT == 1) { v0 = gelu_tanh(v0); v1 = gelu_tanh(v1); }
                if (Rrow) { v0 += Rrow[col]; v1 += Rrow[col + 1]; }
                if (OUTR) { v0 = to_tf32(v0); v1 = to_tf32(v1); }
                *(float2*)(Crow + col) = make_float2(v0, v1);
            }
        }
    }
}

// ---------------- launch ----------------------------------------------------
extern "C" void kernel_launch(void* const* d_in, const int* in_sizes, int n_in,
                              void* d_out, int out_size) {
    const float* x      = (const float*)d_in[0];
    const float* mask   = (const float*)d_in[1];
    const float* cosp   = (const float*)d_in[2];
    const float* sinp   = (const float*)d_in[3];
    const float* qkv_w  = (const float*)d_in[4];
    const float* qkv_b  = (const float*)d_in[5];
    const float* proj_w = (const float*)d_in[6];
    const float* proj_b = (const float*)d_in[7];
    const float* fc1_w  = (const float*)d_in[8];
    const float* fc1_b  = (const float*)d_in[9];
    const float* fc2_w  = (const float*)d_in[10];
    const float* fc2_b  = (const float*)d_in[11];
    const float* ln1_g  = (const float*)d_in[12];
    const float* ln1_b  = (const float*)d_in[13];
    const float* ln2_g  = (const float*)d_in[14];
    const float* ln2_b  = (const float*)d_in[15];
    float* out = (float*)d_out;

    float *p_ln, *p_qkv, *p_ctx, *p_x1, *p_ffn;
    float *p_wqkv, *p_wproj, *p_wfc1, *p_wfc2;
    cudaGetSymbolAddress((void**)&p_ln,   g_ln);
    cudaGetSymbolAddress((void**)&p_qkv,  g_qkv);
    cudaGetSymbolAddress((void**)&p_ctx,  g_ctx);
    cudaGetSymbolAddress((void**)&p_x1,   g_x1);
    cudaGetSymbolAddress((void**)&p_ffn,  g_ffn);
    cudaGetSymbolAddress((void**)&p_wqkv, g_wqkv);
    cudaGetSymbolAddress((void**)&p_wproj,g_wproj);
    cudaGetSymbolAddress((void**)&p_wfc1, g_wfc1);
    cudaGetSymbolAddress((void**)&p_wfc2, g_wfc2);

    const int SMG = 2 * 8192 * 4;                                   // 65536
    const int SMF = (2 * KS_STRIDE + 2 * VS_STRIDE) * 4;            // 176128
    cudaFuncSetAttribute(mma_gemm<0, 0>, cudaFuncAttributeMaxDynamicSharedMemorySize, SMG);
    cudaFuncSetAttribute(mma_gemm<0, 1>, cudaFuncAttributeMaxDynamicSharedMemorySize, SMG);
    cudaFuncSetAttribute(mma_gemm<1, 1>, cudaFuncAttributeMaxDynamicSharedMemorySize, SMG);
    cudaFuncSetAttribute(flash_kernel, cudaFuncAttributeMaxDynamicSharedMemorySize, SMF);

    // 0. round all weights to tf32 in one launch
    {
        int n0 = 3 * HH * HH / 4, n1 = HH * HH / 4;
        int n2 = IDIM * HH / 4,   n3 = HH * IDIM / 4;
        int mx = n2;  // largest
        round_all_kernel<<<dim3((mx + 255) / 256, 4), 256>>>(
            qkv_w, p_wqkv, n0, proj_w, p_wproj, n1,
            fc1_w, p_wfc1, n2, fc2_w, p_wfc2, n3);
    }

    // 1. LN1 (rounded output)
    ln_kernel<<<SS, 256>>>(x, ln1_g, ln1_b, p_ln);

    // 2. QKV = ln @ qkv_w^T + qkv_b  (rounded output)
    mma_gemm<0, 1><<<dim3(3840 / 128, SS / 128), 128, SMG>>>(
        p_ln, HH, p_wqkv, HH, p_qkv, 3 * HH,
        qkv_b, nullptr, 0, 3 * HH, HH);

    // 3. RoPE on q, k in place (rounded output)
    {
        int n = SS * NHEAD * (HDIM / 2);
        rope_kernel<<<(n + 255) / 256, 256>>>(p_qkv, cosp, sinp);
    }

    // 4-6. fused flash attention -> ctx (rounded output)
    flash_kernel<<<dim3(SS / 128, NHEAD), 256, SMF>>>(p_qkv, mask, p_ctx);

    // 7. x1 = x + ctx @ proj_w^T + proj_b  (fp32: residual stream)
    mma_gemm<0, 0><<<dim3(HH / 128, SS / 128), 128, SMG>>>(
        p_ctx, HH, p_wproj, HH, p_x1, HH,
        proj_b, x, HH, HH, HH);

    // 8. LN2 (rounded output)
    ln_kernel<<<SS, 256>>>(p_x1, ln2_g, ln2_b, p_ln);

    // 9. ffn = gelu(ln @ fc1_w^T + fc1_b)  (rounded output)
    mma_gemm<1, 1><<<dim3(IDIM / 128, SS / 128), 128, SMG>>>(
        p_ln, HH, p_wfc1, HH, p_ffn, IDIM,
        fc1_b, nullptr, 0, IDIM, HH);

    // 10. out = x1 + ffn @ fc2_w^T + fc2_b  (fp32: final output)
    mma_gemm<0, 0><<<dim3(HH / 128, SS / 128), 128, SMG>>>(
        p_ffn, IDIM, p_wfc2, IDIM, out, HH,
        fc2_b, p_x1, HH, HH, IDIM);
}

// round 11
// speedup vs baseline: 1.1225x; 1.1225x over previous
#include <cuda_runtime.h>
#include <math.h>
#include <stdint.h>

#define SS 4096
#define HH 1280
#define NHEAD 16
#define HDIM 80
#define IDIM 5120
#define EPSV 1e-6f

// ---------------- scratch (static device memory; no allocs allowed) --------
__device__ float g_ln  [(size_t)SS * HH];
__device__ float g_qkv [(size_t)SS * 3 * HH];
__device__ float g_ctx [(size_t)SS * HH];
__device__ float g_x1  [(size_t)SS * HH];
__device__ float g_ffn [(size_t)SS * IDIM];
// tf32-rounded weight copies
__device__ float g_wqkv[(size_t)3 * HH * HH];
__device__ float g_wproj[(size_t)HH * HH];
__device__ float g_wfc1[(size_t)IDIM * HH];
__device__ float g_wfc2[(size_t)HH * IDIM];

// ---------------- helpers ---------------------------------------------------
__device__ __forceinline__ float to_tf32(float x) {
    float r;
    asm("cvt.rna.tf32.f32 %0, %1;" : "=f"(r) : "f"(x));
    return r;
}
__device__ __forceinline__ float4 cvt4(float4 v) {
    v.x = to_tf32(v.x); v.y = to_tf32(v.y); v.z = to_tf32(v.z); v.w = to_tf32(v.w);
    return v;
}
__device__ __forceinline__ uint32_t smem_u32(const void* p) {
    uint32_t a;
    asm("{ .reg .u64 t; cvta.to.shared.u64 t, %1; cvt.u32.u64 %0, t; }" : "=r"(a) : "l"(p));
    return a;
}
__device__ __forceinline__ void mma_tf32(float* d, uint32_t a0, uint32_t a1,
                                         uint32_t a2, uint32_t a3,
                                         uint32_t b0, uint32_t b1) {
    asm volatile(
        "mma.sync.aligned.m16n8k8.row.col.f32.tf32.tf32.f32 "
        "{%0,%1,%2,%3}, {%4,%5,%6,%7}, {%8,%9}, {%0,%1,%2,%3};"
        : "+f"(d[0]), "+f"(d[1]), "+f"(d[2]), "+f"(d[3])
        : "r"(a0), "r"(a1), "r"(a2), "r"(a3), "r"(b0), "r"(b1));
}
#define CP_ASYNC16(dst, src) \
    asm volatile("cp.async.cg.shared.global [%0], [%1], 16;" :: "r"(dst), "l"(src) : "memory")
#define CP_COMMIT() asm volatile("cp.async.commit_group;" ::: "memory")
#define CP_WAIT(n)  asm volatile("cp.async.wait_group %0;" :: "n"(n) : "memory")

// ---------------- weight rounding (all four in one launch) ------------------
__global__ void round_all_kernel(const float* s0, float* d0, int n0,
                                 const float* s1, float* d1, int n1,
                                 const float* s2, float* d2, int n2,
                                 const float* s3, float* d3, int n3) {
    const float* src; float* dst; int n;
    switch (blockIdx.y) {
        case 0: src = s0; dst = d0; n = n0; break;
        case 1: src = s1; dst = d1; n = n1; break;
        case 2: src = s2; dst = d2; n = n2; break;
        default: src = s3; dst = d3; n = n3; break;
    }
    int i = blockIdx.x * blockDim.x + threadIdx.x;
    if (i < n) ((float4*)dst)[i] = cvt4(((const float4*)src)[i]);
}

// ---------------- reductions ----------------------------------------------
__device__ __forceinline__ float block_reduce_sum(float v) {
    __shared__ float sh_sum[32];
    int lane = threadIdx.x & 31, wid = threadIdx.x >> 5;
    #pragma unroll
    for (int o = 16; o; o >>= 1) v += __shfl_xor_sync(0xffffffffu, v, o);
    if (lane == 0) sh_sum[wid] = v;
    __syncthreads();
    v = (threadIdx.x < (blockDim.x >> 5)) ? sh_sum[threadIdx.x] : 0.f;
    if (wid == 0) {
        #pragma unroll
        for (int o = 16; o; o >>= 1) v += __shfl_xor_sync(0xffffffffu, v, o);
        if (lane == 0) sh_sum[0] = v;
    }
    __syncthreads();
    float r = sh_sum[0];
    __syncthreads();
    return r;
}

// ---------------- layernorm (tf32-rounded output) ---------------------------
__global__ void ln_kernel(const float* __restrict__ x, const float* __restrict__ g,
                          const float* __restrict__ b, float* __restrict__ out) {
    int row = blockIdx.x;
    const float* xr = x + (size_t)row * HH;
    float v[5]; float s = 0.f;
    #pragma unroll
    for (int i = 0; i < 5; i++) { v[i] = xr[threadIdx.x + i * 256]; s += v[i]; }
    float mean = block_reduce_sum(s) * (1.f / HH);
    float vs = 0.f;
    #pragma unroll
    for (int i = 0; i < 5; i++) { float d = v[i] - mean; vs += d * d; }
    float var = block_reduce_sum(vs) * (1.f / HH);
    float inv = rsqrtf(var + EPSV);
    float* o = out + (size_t)row * HH;
    #pragma unroll
    for (int i = 0; i < 5; i++) {
        int c = threadIdx.x + i * 256;
        o[c] = to_tf32((v[i] - mean) * inv * g[c] + b[c]);
    }
}

// ---------------- RoPE (tf32-rounded output) --------------------------------
__global__ void rope_kernel(float* __restrict__ qkv, const float* __restrict__ cs,
                            const float* __restrict__ sn) {
    int idx = blockIdx.x * blockDim.x + threadIdx.x;
    if (idx >= SS * NHEAD * (HDIM / 2)) return;
    int d = idx % (HDIM / 2);
    int h = (idx / (HDIM / 2)) % NHEAD;
    int s = idx / ((HDIM / 2) * NHEAD);
    float c1 = cs[s * HDIM + d], c2 = cs[s * HDIM + d + 40];
    float s1 = sn[s * HDIM + d], s2 = sn[s * HDIM + d + 40];
    size_t base = (size_t)s * 3 * HH + h * HDIM;
    float* qp = qkv + base;
    float a = qp[d], bb = qp[d + 40];
    qp[d]      = to_tf32(a * c1 - bb * s1);
    qp[d + 40] = to_tf32(bb * c2 + a * s2);
    float* kp = qkv + base + HH;
    a = kp[d]; bb = kp[d + 40];
    kp[d]      = to_tf32(a * c1 - bb * s1);
    kp[d + 40] = to_tf32(bb * c2 + a * s2);
}

__device__ __forceinline__ float gelu_tanh(float x) {
    return 0.5f * x * (1.f + tanhf(0.7978845608028654f * (x + 0.044715f * x * x * x)));
}

// ================= flash attention v2 (cp.async double-buffered) ============
#define KSP 84
#define VSP 88
#define KS_STRIDE (128 * KSP)   // 10752
#define VS_STRIDE (128 * VSP)   // 11264
__global__ void __launch_bounds__(256)
flash_kernel(const float* __restrict__ qkv, const float* __restrict__ mask,
             float* __restrict__ ctx) {
    extern __shared__ float fsm[];
    float* Ks = fsm;                         // 2 x KS_STRIDE
    float* Vs = fsm + 2 * KS_STRIDE;         // 2 x VS_STRIDE
    float* Qstage = Vs + VS_STRIDE;          // aliases Vs buf1 (prologue only)
    const uint32_t smb = smem_u32(fsm);

    const int tid  = threadIdx.x;
    const int wid  = tid >> 5;
    const int lane = tid & 31;
    const int g4   = lane >> 2;
    const int kl   = lane & 3;
    const int bm   = blockIdx.x * 128;
    const int h    = blockIdx.y;
    const float scale = rsqrtf((float)HDIM);

    const float* Qb = qkv + h * HDIM;
    const float* Kb = qkv + HH + h * HDIM;
    const float* Vb = qkv + 2 * HH + h * HDIM;

    auto issue = [&](int kv0, int b) {
        uint32_t kbase = smb + (uint32_t)(b * KS_STRIDE) * 4;
        uint32_t vbase = smb + (uint32_t)((2 * KS_STRIDE) + b * VS_STRIDE) * 4;
        #pragma unroll
        for (int i = 0; i < 10; i++) {
            int c = i * 256 + tid;
            int row = c / 20, col = (c % 20) * 4;
            CP_ASYNC16(kbase + (uint32_t)(row * KSP + col) * 4,
                       Kb + (size_t)(kv0 + row) * (3 * HH) + col);
            CP_ASYNC16(vbase + (uint32_t)(row * VSP + col) * 4,
                       Vb + (size_t)(kv0 + row) * (3 * HH) + col);
        }
        CP_COMMIT();
    };

    issue(0, 0);

    {
        const int lr = tid >> 1;
        const int lc = (tid & 1) * 40;
        const float* src = Qb + (size_t)(bm + lr) * (3 * HH) + lc;
        float* dst = Qstage + lr * KSP + lc;
        #pragma unroll
        for (int i = 0; i < 10; i++)
            *(float4*)(dst + i * 4) = *(const float4*)(src + i * 4);
    }
    __syncthreads();
    uint32_t qa[10][4];
    {
        int r0 = wid * 16 + g4;
        #pragma unroll
        for (int ks = 0; ks < 10; ks++) {
            qa[ks][0] = __float_as_uint(Qstage[r0 * KSP + ks * 8 + kl]);
            qa[ks][1] = __float_as_uint(Qstage[(r0 + 8) * KSP + ks * 8 + kl]);
            qa[ks][2] = __float_as_uint(Qstage[r0 * KSP + ks * 8 + kl + 4]);
            qa[ks][3] = __float_as_uint(Qstage[(r0 + 8) * KSP + ks * 8 + kl + 4]);
        }
    }

    float Oa[10][4];
    #pragma unroll
    for (int i = 0; i < 10; i++)
        #pragma unroll
        for (int j = 0; j < 4; j++) Oa[i][j] = 0.f;
    float m0 = -INFINITY, m1 = -INFINITY, l0 = 0.f, l1 = 0.f;

    const float* mrow0 = mask + (size_t)(bm + wid * 16 + g4) * SS;
    const float* mrow1 = mrow0 + (size_t)8 * SS;

    const int src_lo = (lane & ~3) | (kl >> 1);
    const int src_hi = src_lo + 2;

    constexpr int NT = SS / 128;
    for (int s = 0; s < NT; s++) {
        const int buf = s & 1;
        const int kv0 = s * 128;
        __syncthreads();
        if (s + 1 < NT) issue((s + 1) * 128, buf ^ 1);
        if (s + 1 < NT) { CP_WAIT(1); } else { CP_WAIT(0); }
        __syncthreads();

        const float* K_ = Ks + buf * KS_STRIDE;
        const float* V_ = Vs + buf * VS_STRIDE;

        float sa[16][4];
        #pragma unroll
        for (int nt = 0; nt < 16; nt++)
            #pragma unroll
            for (int j = 0; j < 4; j++) sa[nt][j] = 0.f;
        #pragma unroll
        for (int ks = 0; ks < 10; ks++) {
            #pragma unroll
            for (int nt = 0; nt < 16; nt++) {
                uint32_t b0 = __float_as_uint(K_[(nt * 8 + g4) * KSP + ks * 8 + kl]);
                uint32_t b1 = __float_as_uint(K_[(nt * 8 + g4) * KSP + ks * 8 + kl + 4]);
                mma_tf32(sa[nt], qa[ks][0], qa[ks][1], qa[ks][2], qa[ks][3], b0, b1);
            }
        }

        float tmx0 = -INFINITY, tmx1 = -INFINITY;
        #pragma unroll
        for (int nt = 0; nt < 16; nt++) {
            float2 mk0 = *(const float2*)(mrow0 + kv0 + nt * 8 + 2 * kl);
            float2 mk1 = *(const float2*)(mrow1 + kv0 + nt * 8 + 2 * kl);
            sa[nt][0] = sa[nt][0] * scale + mk0.x;
            sa[nt][1] = sa[nt][1] * scale + mk0.y;
            sa[nt][2] = sa[nt][2] * scale + mk1.x;
            sa[nt][3] = sa[nt][3] * scale + mk1.y;
            tmx0 = fmaxf(tmx0, fmaxf(sa[nt][0], sa[nt][1]));
            tmx1 = fmaxf(tmx1, fmaxf(sa[nt][2], sa[nt][3]));
        }
        tmx0 = fmaxf(tmx0, __shfl_xor_sync(0xffffffffu, tmx0, 1));
        tmx0 = fmaxf(tmx0, __shfl_xor_sync(0xffffffffu, tmx0, 2));
        tmx1 = fmaxf(tmx1, __shfl_xor_sync(0xffffffffu, tmx1, 1));
        tmx1 = fmaxf(tmx1, __shfl_xor_sync(0xffffffffu, tmx1, 2));

        float nm0 = fmaxf(m0, tmx0), nm1 = fmaxf(m1, tmx1);
        float f0 = __expf(m0 - nm0), f1 = __expf(m1 - nm1);
        m0 = nm0; m1 = nm1;

        float ts0 = 0.f, ts1 = 0.f;
        #pragma unroll
        for (int nt = 0; nt < 16; nt++) {
            sa[nt][0] = __expf(sa[nt][0] - nm0);
            sa[nt][1] = __expf(sa[nt][1] - nm0);
            sa[nt][2] = __expf(sa[nt][2] - nm1);
            sa[nt][3] = __expf(sa[nt][3] - nm1);
            ts0 += sa[nt][0] + sa[nt][1];
            ts1 += sa[nt][2] + sa[nt][3];
        }
        ts0 += __shfl_xor_sync(0xffffffffu, ts0, 1);
        ts0 += __shfl_xor_sync(0xffffffffu, ts0, 2);
        ts1 += __shfl_xor_sync(0xffffffffu, ts1, 1);
        ts1 += __shfl_xor_sync(0xffffffffu, ts1, 2);
        l0 = l0 * f0 + ts0;
        l1 = l1 * f1 + ts1;

        #pragma unroll
        for (int no = 0; no < 10; no++) {
            Oa[no][0] *= f0; Oa[no][1] *= f0;
            Oa[no][2] *= f1; Oa[no][3] *= f1;
        }

        #pragma unroll
        for (int nt = 0; nt < 16; nt++) {
            float p0 = to_tf32(sa[nt][0]), p1 = to_tf32(sa[nt][1]);
            float p2 = to_tf32(sa[nt][2]), p3 = to_tf32(sa[nt][3]);
            float a0l = __shfl_sync(0xffffffffu, p0, src_lo);
            float a0h = __shfl_sync(0xffffffffu, p1, src_lo);
            float a1l = __shfl_sync(0xffffffffu, p2, src_lo);
            float a1h = __shfl_sync(0xffffffffu, p3, src_lo);
            float a2l = __shfl_sync(0xffffffffu, p0, src_hi);
            float a2h = __shfl_sync(0xffffffffu, p1, src_hi);
            float a3l = __shfl_sync(0xffffffffu, p2, src_hi);
            float a3h = __shfl_sync(0xffffffffu, p3, src_hi);
            bool odd = (kl & 1);
            uint32_t A0 = __float_as_uint(odd ? a0h : a0l);
            uint32_t A1 = __float_as_uint(odd ? a1h : a1l);
            uint32_t A2 = __float_as_uint(odd ? a2h : a2l);
            uint32_t A3 = __float_as_uint(odd ? a3h : a3l);
            #pragma unroll
            for (int no = 0; no < 10; no++) {
                uint32_t b0 = __float_as_uint(V_[(nt * 8 + kl) * VSP + no * 8 + g4]);
                uint32_t b1 = __float_as_uint(V_[(nt * 8 + kl + 4) * VSP + no * 8 + g4]);
                mma_tf32(Oa[no], A0, A1, A2, A3, b0, b1);
            }
        }
    }

    float i0 = 1.f / l0, i1 = 1.f / l1;
    int r0 = bm + wid * 16 + g4;
    float* c0p = ctx + (size_t)r0 * HH + h * HDIM;
    float* c1p = c0p + (size_t)8 * HH;
    #pragma unroll
    for (int no = 0; no < 10; no++) {
        *(float2*)(c0p + no * 8 + 2 * kl) =
            make_float2(to_tf32(Oa[no][0] * i0), to_tf32(Oa[no][1] * i0));
        *(float2*)(c1p + no * 8 + 2 * kl) =
            make_float2(to_tf32(Oa[no][2] * i1), to_tf32(Oa[no][3] * i1));
    }
}

// ================= TF32 GEMM v5: 3-stage cp.async + frag double-buffer ======
// Reverts R10's 2-stage experiment (pipeline-depth-bound, not occupancy-bound).
// Adds register double-buffering of fragments: LDS for ko+1 overlap MMAs of ko.
template<int ACT, int OUTR>
__global__ void __launch_bounds__(128)
mma_gemm(const float* __restrict__ A, int lda,
         const float* __restrict__ B, int ldb,
         float* __restrict__ C, int ldc,
         const float* __restrict__ bias,
         const float* __restrict__ Rsd, int ldr,
         int N, int K) {
    extern __shared__ float sm[];           // 3 stages x 8192 floats
    const uint32_t smb = smem_u32(sm);

    const int tid = threadIdx.x;
    const int wid = tid >> 5;
    const int lane = tid & 31;
    const int g4 = lane >> 2;
    const int kl = lane & 3;
    const int warpM = (wid >> 1) * 64;
    const int warpN = (wid & 1) * 64;
    const int bm = blockIdx.y * 128;
    const int bn = blockIdx.x * 128;

    float acc[4][8][4];
    #pragma unroll
    for (int i = 0; i < 4; i++)
        #pragma unroll
        for (int j = 0; j < 8; j++)
            #pragma unroll
            for (int q = 0; q < 4; q++) acc[i][j][q] = 0.f;

    auto issue = [&](int k0, int st) {
        uint32_t ab = smb + st * 32768;
        uint32_t bb = ab + 16384;
        #pragma unroll
        for (int i = 0; i < 8; i++) {
            int idx = i * 128 + tid;
            int row = idx >> 3, col = idx & 7;
            uint32_t sw = (uint32_t)((col ^ (row & 7)) << 4);
            CP_ASYNC16(ab + row * 128 + sw, A + (size_t)(bm + row) * lda + k0 + col * 4);
            CP_ASYNC16(bb + row * 128 + sw, B + (size_t)(bn + row) * ldb + k0 + col * 4);
        }
        CP_COMMIT();
    };

    uint32_t af[2][4][4], bf[2][8][2];
    auto ldfrag = [&](const float* As, const float* Bs, int ko, int fb) {
        const int cc0 = (((ko * 2)     ^ g4) << 2) | kl;
        const int cc1 = (((ko * 2 + 1) ^ g4) << 2) | kl;
        #pragma unroll
        for (int mt = 0; mt < 4; mt++) {
            int m = warpM + mt * 16 + g4;
            af[fb][mt][0] = __float_as_uint(As[m * 32 + cc0]);
            af[fb][mt][1] = __float_as_uint(As[(m + 8) * 32 + cc0]);
            af[fb][mt][2] = __float_as_uint(As[m * 32 + cc1]);
            af[fb][mt][3] = __float_as_uint(As[(m + 8) * 32 + cc1]);
        }
        #pragma unroll
        for (int nt = 0; nt < 8; nt++) {
            int n = warpN + nt * 8 + g4;
            bf[fb][nt][0] = __float_as_uint(Bs[n * 32 + cc0]);
            bf[fb][nt][1] = __float_as_uint(Bs[n * 32 + cc1]);
        }
    };
    auto domma = [&](int fb) {
        #pragma unroll
        for (int mt = 0; mt < 4; mt++)
            #pragma unroll
            for (int nt = 0; nt < 8; nt++)
                mma_tf32(acc[mt][nt], af[fb][mt][0], af[fb][mt][1],
                         af[fb][mt][2], af[fb][mt][3], bf[fb][nt][0], bf[fb][nt][1]);
    };

    auto compute = [&](int st) {
        const float* As = sm + st * 8192;
        const float* Bs = As + 4096;
        ldfrag(As, Bs, 0, 0);
        #pragma unroll
        for (int ko = 0; ko < 4; ko++) {
            if (ko < 3) ldfrag(As, Bs, ko + 1, (ko + 1) & 1);  // overlaps MMAs below
            domma(ko & 1);
        }
    };

    const int nst = K / 32;
    issue(0, 0);
    if (nst > 1) issue(32, 1);
    int st = 0;
    for (int s = 0; s < nst; s++) {
        if (s + 1 < nst) { CP_WAIT(1); } else { CP_WAIT(0); }
        __syncthreads();
        if (s + 2 < nst) {
            int st2 = st + 2; if (st2 >= 3) st2 -= 3;
            issue((s + 2) * 32, st2);
        }
        compute(st);
        if (++st == 3) st = 0;
    }

    // ---- epilogue ----
    #pragma unroll
    for (int mt = 0; mt < 4; mt++) {
        #pragma unroll
        for (int rr = 0; rr < 2; rr++) {
            int r_ = bm + warpM + mt * 16 + g4 + rr * 8;
            float* Crow = C + (size_t)r_ * ldc;
            const float* Rrow = Rsd ? (Rsd + (size_t)r_ * ldr) : nullptr;
            #pragma unroll
            for (int nt = 0; nt < 8; nt++) {
                int col = bn + warpN + nt * 8 + kl * 2;
                float v0 = acc[mt][nt][rr * 2 + 0];
                float v1 = acc[mt][nt][rr * 2 + 1];
                if (bias) { v0 += bias[col]; v1 += bias[col + 1]; }
                if (ACT == 1) { v0 = gelu_tanh(v0); v1 = gelu_tanh(v1); }
                if (Rrow) { v0 += Rrow[col]; v1 += Rrow[col + 1]; }
                if (OUTR) { v0 = to_tf32(v0); v1 = to_tf32(v1); }
                *(float2*)(Crow + col) = make_float2(v0, v1);
            }
        }
    }
}

// ---------------- launch ----------------------------------------------------
extern "C" void kernel_launch(void* const* d_in, const int* in_sizes, int n_in,
                              void* d_out, int out_size) {
    const float* x      = (const float*)d_in[0];
    const float* mask   = (const float*)d_in[1];
    const float* cosp   = (const float*)d_in[2];
    const float* sinp   = (const float*)d_in[3];
    const float* qkv_w  = (const float*)d_in[4];
    const float* qkv_b  = (const float*)d_in[5];
    const float* proj_w = (const float*)d_in[6];
    const float* proj_b = (const float*)d_in[7];
    const float* fc1_w  = (const float*)d_in[8];
    const float* fc1_b  = (const float*)d_in[9];
    const float* fc2_w  = (const float*)d_in[10];
    const float* fc2_b  = (const float*)d_in[11];
    const float* ln1_g  = (const float*)d_in[12];
    const float* ln1_b  = (const float*)d_in[13];
    const float* ln2_g  = (const float*)d_in[14];
    const float* ln2_b  = (const float*)d_in[15];
    float* out = (float*)d_out;

    float *p_ln, *p_qkv, *p_ctx, *p_x1, *p_ffn;
    float *p_wqkv, *p_wproj, *p_wfc1, *p_wfc2;
    cudaGetSymbolAddress((void**)&p_ln,   g_ln);
    cudaGetSymbolAddress((void**)&p_qkv,  g_qkv);
    cudaGetSymbolAddress((void**)&p_ctx,  g_ctx);
    cudaGetSymbolAddress((void**)&p_x1,   g_x1);
    cudaGetSymbolAddress((void**)&p_ffn,  g_ffn);
    cudaGetSymbolAddress((void**)&p_wqkv, g_wqkv);
    cudaGetSymbolAddress((void**)&p_wproj,g_wproj);
    cudaGetSymbolAddress((void**)&p_wfc1, g_wfc1);
    cudaGetSymbolAddress((void**)&p_wfc2, g_wfc2);

    const int SMG = 3 * 8192 * 4;                                   // 98304
    const int SMF = (2 * KS_STRIDE + 2 * VS_STRIDE) * 4;            // 176128
    cudaFuncSetAttribute(mma_gemm<0, 0>, cudaFuncAttributeMaxDynamicSharedMemorySize, SMG);
    cudaFuncSetAttribute(mma_gemm<0, 1>, cudaFuncAttributeMaxDynamicSharedMemorySize, SMG);
    cudaFuncSetAttribute(mma_gemm<1, 1>, cudaFuncAttributeMaxDynamicSharedMemorySize, SMG);
    cudaFuncSetAttribute(flash_kernel, cudaFuncAttributeMaxDynamicSharedMemorySize, SMF);

    // 0. round all weights to tf32 in one launch
    {
        int n0 = 3 * HH * HH / 4, n1 = HH * HH / 4;
        int n2 = IDIM * HH / 4,   n3 = HH * IDIM / 4;
        int mx = n2;  // largest
        round_all_kernel<<<dim3((mx + 255) / 256, 4), 256>>>(
            qkv_w, p_wqkv, n0, proj_w, p_wproj, n1,
            fc1_w, p_wfc1, n2, fc2_w, p_wfc2, n3);
    }

    // 1. LN1 (rounded output)
    ln_kernel<<<SS, 256>>>(x, ln1_g, ln1_b, p_ln);

    // 2. QKV = ln @ qkv_w^T + qkv_b  (rounded output)
    mma_gemm<0, 1><<<dim3(3840 / 128, SS / 128), 128, SMG>>>(
        p_ln, HH, p_wqkv, HH, p_qkv, 3 * HH,
        qkv_b, nullptr, 0, 3 * HH, HH);

    // 3. RoPE on q, k in place (rounded output)
    {
        int n = SS * NHEAD * (HDIM / 2);
        rope_kernel<<<(n + 255) / 256, 256>>>(p_qkv, cosp, sinp);
    }

    // 4-6. fused flash attention -> ctx (rounded output)
    flash_kernel<<<dim3(SS / 128, NHEAD), 256, SMF>>>(p_qkv, mask, p_ctx);

    // 7. x1 = x + ctx @ proj_w^T + proj_b  (fp32: residual stream)
    mma_gemm<0, 0><<<dim3(HH / 128, SS / 128), 128, SMG>>>(
        p_ctx, HH, p_wproj, HH, p_x1, HH,
        proj_b, x, HH, HH, HH);

    // 8. LN2 (rounded output)
    ln_kernel<<<SS, 256>>>(p_x1, ln2_g, ln2_b, p_ln);

    // 9. ffn = gelu(ln @ fc1_w^T + fc1_b)  (rounded output)
    mma_gemm<1, 1><<<dim3(IDIM / 128, SS / 128), 128, SMG>>>(
        p_ln, HH, p_wfc1, HH, p_ffn, IDIM,
        fc1_b, nullptr, 0, IDIM, HH);

    // 10. out = x1 + ffn @ fc2_w^T + fc2_b  (fp32: final output)
    mma_gemm<0, 0><<<dim3(HH / 128, SS / 128), 128, SMG>>>(
        p_ffn, IDIM, p_wfc2, IDIM, out, HH,
        fc2_b, p_x1, HH, HH, IDIM);
}

// round 12
// speedup vs baseline: 1.3766x; 1.2264x over previous
#include <cuda_runtime.h>
#include <cuda_bf16.h>
#include <math.h>
#include <stdint.h>

#define SS 4096
#define HH 1280
#define NHEAD 16
#define HDIM 80
#define IDIM 5120
#define EPSV 1e-6f

// ---------------- scratch (static device memory; no allocs allowed) --------
__device__ float g_ln  [(size_t)SS * HH];
__device__ float g_qkv [(size_t)SS * 3 * HH];
__device__ float g_ctx [(size_t)SS * HH];
__device__ float g_x1  [(size_t)SS * HH];
__device__ float g_ffn [(size_t)SS * IDIM];
// tf32-rounded weight copies
__device__ float g_wqkv[(size_t)3 * HH * HH];
__device__ float g_wproj[(size_t)HH * HH];
__device__ float g_wfc1[(size_t)IDIM * HH];
__device__ float g_wfc2[(size_t)HH * IDIM];
// bf16 attention operands
__device__ __nv_bfloat16 g_qbf[(size_t)SS * HH];
__device__ __nv_bfloat16 g_kbf[(size_t)SS * HH];
__device__ __nv_bfloat16 g_vt [(size_t)NHEAD * HDIM * SS];   // [h][hd][kv]

// ---------------- helpers ---------------------------------------------------
__device__ __forceinline__ float to_tf32(float x) {
    float r;
    asm("cvt.rna.tf32.f32 %0, %1;" : "=f"(r) : "f"(x));
    return r;
}
__device__ __forceinline__ float4 cvt4(float4 v) {
    v.x = to_tf32(v.x); v.y = to_tf32(v.y); v.z = to_tf32(v.z); v.w = to_tf32(v.w);
    return v;
}
__device__ __forceinline__ uint32_t smem_u32(const void* p) {
    uint32_t a;
    asm("{ .reg .u64 t; cvta.to.shared.u64 t, %1; cvt.u32.u64 %0, t; }" : "=r"(a) : "l"(p));
    return a;
}
__device__ __forceinline__ void mma_tf32(float* d, uint32_t a0, uint32_t a1,
                                         uint32_t a2, uint32_t a3,
                                         uint32_t b0, uint32_t b1) {
    asm volatile(
        "mma.sync.aligned.m16n8k8.row.col.f32.tf32.tf32.f32 "
        "{%0,%1,%2,%3}, {%4,%5,%6,%7}, {%8,%9}, {%0,%1,%2,%3};"
        : "+f"(d[0]), "+f"(d[1]), "+f"(d[2]), "+f"(d[3])
        : "r"(a0), "r"(a1), "r"(a2), "r"(a3), "r"(b0), "r"(b1));
}
__device__ __forceinline__ void mma_bf16(float* d, uint32_t a0, uint32_t a1,
                                         uint32_t a2, uint32_t a3,
                                         uint32_t b0, uint32_t b1) {
    asm volatile(
        "mma.sync.aligned.m16n8k16.row.col.f32.bf16.bf16.f32 "
        "{%0,%1,%2,%3}, {%4,%5,%6,%7}, {%8,%9}, {%0,%1,%2,%3};"
        : "+f"(d[0]), "+f"(d[1]), "+f"(d[2]), "+f"(d[3])
        : "r"(a0), "r"(a1), "r"(a2), "r"(a3), "r"(b0), "r"(b1));
}
__device__ __forceinline__ uint32_t packbf(float hi, float lo) {
    uint32_t r;
    asm("cvt.rn.bf16x2.f32 %0, %1, %2;" : "=r"(r) : "f"(hi), "f"(lo));
    return r;
}
#define CP_ASYNC16(dst, src) \
    asm volatile("cp.async.cg.shared.global [%0], [%1], 16;" :: "r"(dst), "l"(src) : "memory")
#define CP_COMMIT() asm volatile("cp.async.commit_group;" ::: "memory")
#define CP_WAIT(n)  asm volatile("cp.async.wait_group %0;" :: "n"(n) : "memory")

// ---------------- weight rounding (all four in one launch) ------------------
__global__ void round_all_kernel(const float* s0, float* d0, int n0,
                                 const float* s1, float* d1, int n1,
                                 const float* s2, float* d2, int n2,
                                 const float* s3, float* d3, int n3) {
    const float* src; float* dst; int n;
    switch (blockIdx.y) {
        case 0: src = s0; dst = d0; n = n0; break;
        case 1: src = s1; dst = d1; n = n1; break;
        case 2: src = s2; dst = d2; n = n2; break;
        default: src = s3; dst = d3; n = n3; break;
    }
    int i = blockIdx.x * blockDim.x + threadIdx.x;
    if (i < n) ((float4*)dst)[i] = cvt4(((const float4*)src)[i]);
}

// ---------------- bf16 conversions ------------------------------------------
// q, k natural layout [s][1280] bf16 (blockIdx.y: 0 = q, 1 = k)
__global__ void cvt_qk_kernel(const float* __restrict__ qkv,
                              __nv_bfloat16* __restrict__ qbf,
                              __nv_bfloat16* __restrict__ kbf) {
    int i = blockIdx.x * 256 + threadIdx.x;             // index of float4
    const int n4 = SS * HH / 4;
    if (i >= n4) return;
    int s = i / (HH / 4), c4 = i % (HH / 4);
    const float* src = qkv + (size_t)s * (3 * HH) + blockIdx.y * HH + c4 * 4;
    float4 v = *(const float4*)src;
    uint32_t p0 = packbf(v.y, v.x);
    uint32_t p1 = packbf(v.w, v.z);
    __nv_bfloat16* dst = (blockIdx.y ? kbf : qbf) + (size_t)s * HH + c4 * 4;
    *(uint2*)dst = make_uint2(p0, p1);
}
// V transposed per head: vt[h][hd][kv]. grid (SS/128, HDIM/16, NHEAD), block (16,16)
__global__ void cvt_vt_kernel(const float* __restrict__ qkv,
                              __nv_bfloat16* __restrict__ vt) {
    __shared__ float tile[16][129];
    int h = blockIdx.z, hd0 = blockIdx.y * 16, kv0 = blockIdx.x * 128;
    int tx = threadIdx.x, ty = threadIdx.y;
    #pragma unroll
    for (int j = 0; j < 8; j++) {
        int s = kv0 + ty + 16 * j;
        tile[tx][ty + 16 * j] = qkv[(size_t)s * (3 * HH) + 2 * HH + h * HDIM + hd0 + tx];
    }
    __syncthreads();
    #pragma unroll
    for (int j = 0; j < 8; j++) {
        int kv = tx + 16 * j;
        vt[((size_t)h * HDIM + hd0 + ty) * SS + kv0 + kv] = __float2bfloat16(tile[ty][kv]);
    }
}

// ---------------- reductions ----------------------------------------------
__device__ __forceinline__ float block_reduce_sum(float v) {
    __shared__ float sh_sum[32];
    int lane = threadIdx.x & 31, wid = threadIdx.x >> 5;
    #pragma unroll
    for (int o = 16; o; o >>= 1) v += __shfl_xor_sync(0xffffffffu, v, o);
    if (lane == 0) sh_sum[wid] = v;
    __syncthreads();
    v = (threadIdx.x < (blockDim.x >> 5)) ? sh_sum[threadIdx.x] : 0.f;
    if (wid == 0) {
        #pragma unroll
        for (int o = 16; o; o >>= 1) v += __shfl_xor_sync(0xffffffffu, v, o);
        if (lane == 0) sh_sum[0] = v;
    }
    __syncthreads();
    float r = sh_sum[0];
    __syncthreads();
    return r;
}

// ---------------- layernorm (tf32-rounded output) ---------------------------
__global__ void ln_kernel(const float* __restrict__ x, const float* __restrict__ g,
                          const float* __restrict__ b, float* __restrict__ out) {
    int row = blockIdx.x;
    const float* xr = x + (size_t)row * HH;
    float v[5]; float s = 0.f;
    #pragma unroll
    for (int i = 0; i < 5; i++) { v[i] = xr[threadIdx.x + i * 256]; s += v[i]; }
    float mean = block_reduce_sum(s) * (1.f / HH);
    float vs = 0.f;
    #pragma unroll
    for (int i = 0; i < 5; i++) { float d = v[i] - mean; vs += d * d; }
    float var = block_reduce_sum(vs) * (1.f / HH);
    float inv = rsqrtf(var + EPSV);
    float* o = out + (size_t)row * HH;
    #pragma unroll
    for (int i = 0; i < 5; i++) {
        int c = threadIdx.x + i * 256;
        o[c] = to_tf32((v[i] - mean) * inv * g[c] + b[c]);
    }
}

// ---------------- RoPE (tf32-rounded output) --------------------------------
__global__ void rope_kernel(float* __restrict__ qkv, const float* __restrict__ cs,
                            const float* __restrict__ sn) {
    int idx = blockIdx.x * blockDim.x + threadIdx.x;
    if (idx >= SS * NHEAD * (HDIM / 2)) return;
    int d = idx % (HDIM / 2);
    int h = (idx / (HDIM / 2)) % NHEAD;
    int s = idx / ((HDIM / 2) * NHEAD);
    float c1 = cs[s * HDIM + d], c2 = cs[s * HDIM + d + 40];
    float s1 = sn[s * HDIM + d], s2 = sn[s * HDIM + d + 40];
    size_t base = (size_t)s * 3 * HH + h * HDIM;
    float* qp = qkv + base;
    float a = qp[d], bb = qp[d + 40];
    qp[d]      = to_tf32(a * c1 - bb * s1);
    qp[d + 40] = to_tf32(bb * c2 + a * s2);
    float* kp = qkv + base + HH;
    a = kp[d]; bb = kp[d + 40];
    kp[d]      = to_tf32(a * c1 - bb * s1);
    kp[d + 40] = to_tf32(bb * c2 + a * s2);
}

__device__ __forceinline__ float gelu_tanh(float x) {
    return 0.5f * x * (1.f + tanhf(0.7978845608028654f * (x + 0.044715f * x * x * x)));
}

// ================= flash attention v3 (bf16 m16n8k16) =======================
// grid (SS/64, NHEAD), 128 threads = 4 warps x 16 Q rows, full 128-KV width.
// K tile: [128 kv][88 bf16] (stride 176B; frag banks 12*g4+kl distinct).
// V tile: [80 hd][136 bf16] transposed (stride 272B; banks 4*g4+kl distinct).
// Q frags direct from global bf16. PV A-frags come straight from QK accums
// via cvt.bf16x2 (no shuffles).
#define KR 88
#define VR 136
#define KB_BYTES (128 * KR * 2)   // 22528
#define VB_BYTES (HDIM * VR * 2)  // 21760
__global__ void __launch_bounds__(128)
flash_kernel(const __nv_bfloat16* __restrict__ qbf,
             const __nv_bfloat16* __restrict__ kbf,
             const __nv_bfloat16* __restrict__ vt,
             const float* __restrict__ mask, float* __restrict__ ctx) {
    extern __shared__ char fsm[];
    const uint32_t smb = smem_u32(fsm);

    const int tid  = threadIdx.x;
    const int wid  = tid >> 5;
    const int lane = tid & 31;
    const int g4   = lane >> 2;
    const int kl   = lane & 3;
    const int bm   = blockIdx.x * 64;
    const int h    = blockIdx.y;
    const float scale = rsqrtf((float)HDIM);

    auto issue = [&](int kv0, int b) {
        uint32_t kb = smb + b * KB_BYTES;
        uint32_t vb = smb + 2 * KB_BYTES + b * VB_BYTES;
        const __nv_bfloat16* ks = kbf + (size_t)kv0 * HH + h * HDIM;
        #pragma unroll
        for (int i = 0; i < 10; i++) {
            int c = i * 128 + tid;
            int row = c / 10, ch = c % 10;
            CP_ASYNC16(kb + (uint32_t)(row * (KR * 2) + ch * 16),
                       ks + (size_t)row * HH + ch * 8);
        }
        const __nv_bfloat16* vs = vt + (size_t)h * HDIM * SS + kv0;
        #pragma unroll
        for (int i = 0; i < 10; i++) {
            int c = i * 128 + tid;
            int row = c / 16, ch = c % 16;
            CP_ASYNC16(vb + (uint32_t)(row * (VR * 2) + ch * 16),
                       vs + (size_t)row * SS + ch * 8);
        }
        CP_COMMIT();
    };

    issue(0, 0);

    // ---- Q fragments direct from global (bf16 pairs) ----
    uint32_t qa[5][4];
    {
        int r0 = bm + wid * 16 + g4;
        const __nv_bfloat16* q0 = qbf + (size_t)r0 * HH + h * HDIM;
        const __nv_bfloat16* q1 = q0 + (size_t)8 * HH;
        #pragma unroll
        for (int ks = 0; ks < 5; ks++) {
            qa[ks][0] = *(const uint32_t*)(q0 + ks * 16 + 2 * kl);
            qa[ks][1] = *(const uint32_t*)(q1 + ks * 16 + 2 * kl);
            qa[ks][2] = *(const uint32_t*)(q0 + ks * 16 + 8 + 2 * kl);
            qa[ks][3] = *(const uint32_t*)(q1 + ks * 16 + 8 + 2 * kl);
        }
    }

    float Oa[10][4];
    #pragma unroll
    for (int i = 0; i < 10; i++)
        #pragma unroll
        for (int j = 0; j < 4; j++) Oa[i][j] = 0.f;
    float m0 = -INFINITY, m1 = -INFINITY, l0 = 0.f, l1 = 0.f;

    const float* mrow0 = mask + (size_t)(bm + wid * 16 + g4) * SS;
    const float* mrow1 = mrow0 + (size_t)8 * SS;

    constexpr int NT = SS / 128;
    for (int s = 0; s < NT; s++) {
        const int buf = s & 1;
        const int kv0 = s * 128;
        __syncthreads();
        if (s + 1 < NT) issue((s + 1) * 128, buf ^ 1);
        if (s + 1 < NT) { CP_WAIT(1); } else { CP_WAIT(0); }
        __syncthreads();

        const __nv_bfloat16* K_ = (const __nv_bfloat16*)(fsm + buf * KB_BYTES);
        const __nv_bfloat16* V_ = (const __nv_bfloat16*)(fsm + 2 * KB_BYTES + buf * VB_BYTES);

        // ---- S = Q K^T (bf16 k16: 5 ks x 16 nt) ----
        float sa[16][4];
        #pragma unroll
        for (int nt = 0; nt < 16; nt++)
            #pragma unroll
            for (int j = 0; j < 4; j++) sa[nt][j] = 0.f;
        #pragma unroll
        for (int ks = 0; ks < 5; ks++) {
            #pragma unroll
            for (int nt = 0; nt < 16; nt++) {
                uint32_t b0 = *(const uint32_t*)(K_ + (nt * 8 + g4) * KR + ks * 16 + 2 * kl);
                uint32_t b1 = *(const uint32_t*)(K_ + (nt * 8 + g4) * KR + ks * 16 + 8 + 2 * kl);
                mma_bf16(sa[nt], qa[ks][0], qa[ks][1], qa[ks][2], qa[ks][3], b0, b1);
            }
        }

        // ---- scale + mask + row max ----
        float tmx0 = -INFINITY, tmx1 = -INFINITY;
        #pragma unroll
        for (int nt = 0; nt < 16; nt++) {
            float2 mk0 = *(const float2*)(mrow0 + kv0 + nt * 8 + 2 * kl);
            float2 mk1 = *(const float2*)(mrow1 + kv0 + nt * 8 + 2 * kl);
            sa[nt][0] = sa[nt][0] * scale + mk0.x;
            sa[nt][1] = sa[nt][1] * scale + mk0.y;
            sa[nt][2] = sa[nt][2] * scale + mk1.x;
            sa[nt][3] = sa[nt][3] * scale + mk1.y;
            tmx0 = fmaxf(tmx0, fmaxf(sa[nt][0], sa[nt][1]));
            tmx1 = fmaxf(tmx1, fmaxf(sa[nt][2], sa[nt][3]));
        }
        tmx0 = fmaxf(tmx0, __shfl_xor_sync(0xffffffffu, tmx0, 1));
        tmx0 = fmaxf(tmx0, __shfl_xor_sync(0xffffffffu, tmx0, 2));
        tmx1 = fmaxf(tmx1, __shfl_xor_sync(0xffffffffu, tmx1, 1));
        tmx1 = fmaxf(tmx1, __shfl_xor_sync(0xffffffffu, tmx1, 2));

        float nm0 = fmaxf(m0, tmx0), nm1 = fmaxf(m1, tmx1);
        float f0 = __expf(m0 - nm0), f1 = __expf(m1 - nm1);
        m0 = nm0; m1 = nm1;

        // ---- exp + row sum ----
        float ts0 = 0.f, ts1 = 0.f;
        #pragma unroll
        for (int nt = 0; nt < 16; nt++) {
            sa[nt][0] = __expf(sa[nt][0] - nm0);
            sa[nt][1] = __expf(sa[nt][1] - nm0);
            sa[nt][2] = __expf(sa[nt][2] - nm1);
            sa[nt][3] = __expf(sa[nt][3] - nm1);
            ts0 += sa[nt][0] + sa[nt][1];
            ts1 += sa[nt][2] + sa[nt][3];
        }
        ts0 += __shfl_xor_sync(0xffffffffu, ts0, 1);
        ts0 += __shfl_xor_sync(0xffffffffu, ts0, 2);
        ts1 += __shfl_xor_sync(0xffffffffu, ts1, 1);
        ts1 += __shfl_xor_sync(0xffffffffu, ts1, 2);
        l0 = l0 * f0 + ts0;
        l1 = l1 * f1 + ts1;

        // ---- rescale O ----
        #pragma unroll
        for (int no = 0; no < 10; no++) {
            Oa[no][0] *= f0; Oa[no][1] *= f0;
            Oa[no][2] *= f1; Oa[no][3] *= f1;
        }

        // ---- O += P * V : k16 A-frags are just packed accumulators ----
        #pragma unroll
        for (int g = 0; g < 8; g++) {
            uint32_t A0 = packbf(sa[2 * g][1],     sa[2 * g][0]);
            uint32_t A1 = packbf(sa[2 * g][3],     sa[2 * g][2]);
            uint32_t A2 = packbf(sa[2 * g + 1][1], sa[2 * g + 1][0]);
            uint32_t A3 = packbf(sa[2 * g + 1][3], sa[2 * g + 1][2]);
            #pragma unroll
            for (int no = 0; no < 10; no++) {
                uint32_t b0 = *(const uint32_t*)(V_ + (no * 8 + g4) * VR + g * 16 + 2 * kl);
                uint32_t b1 = *(const uint32_t*)(V_ + (no * 8 + g4) * VR + g * 16 + 8 + 2 * kl);
                mma_bf16(Oa[no], A0, A1, A2, A3, b0, b1);
            }
        }
    }

    // ---- epilogue: O / l -> ctx (tf32-rounded: proj GEMM A operand) ----
    float i0 = 1.f / l0, i1 = 1.f / l1;
    int r0 = bm + wid * 16 + g4;
    float* c0p = ctx + (size_t)r0 * HH + h * HDIM;
    float* c1p = c0p + (size_t)8 * HH;
    #pragma unroll
    for (int no = 0; no < 10; no++) {
        *(float2*)(c0p + no * 8 + 2 * kl) =
            make_float2(to_tf32(Oa[no][0] * i0), to_tf32(Oa[no][1] * i0));
        *(float2*)(c1p + no * 8 + 2 * kl) =
            make_float2(to_tf32(Oa[no][2] * i1), to_tf32(Oa[no][3] * i1));
    }
}

// ================= TF32 GEMM v5: 3-stage cp.async + frag double-buffer ======
template<int ACT, int OUTR>
__global__ void __launch_bounds__(128)
mma_gemm(const float* __restrict__ A, int lda,
         const float* __restrict__ B, int ldb,
         float* __restrict__ C, int ldc,
         const float* __restrict__ bias,
         const float* __restrict__ Rsd, int ldr,
         int N, int K) {
    extern __shared__ float sm[];           // 3 stages x 8192 floats
    const uint32_t smb = smem_u32(sm);

    const int tid = threadIdx.x;
    const int wid = tid >> 5;
    const int lane = tid & 31;
    const int g4 = lane >> 2;
    const int kl = lane & 3;
    const int warpM = (wid >> 1) * 64;
    const int warpN = (wid & 1) * 64;
    const int bm = blockIdx.y * 128;
    const int bn = blockIdx.x * 128;

    float acc[4][8][4];
    #pragma unroll
    for (int i = 0; i < 4; i++)
        #pragma unroll
        for (int j = 0; j < 8; j++)
            #pragma unroll
            for (int q = 0; q < 4; q++) acc[i][j][q] = 0.f;

    auto issue = [&](int k0, int st) {
        uint32_t ab = smb + st * 32768;
        uint32_t bb = ab + 16384;
        #pragma unroll
        for (int i = 0; i < 8; i++) {
            int idx = i * 128 + tid;
            int row = idx >> 3, col = idx & 7;
            uint32_t sw = (uint32_t)((col ^ (row & 7)) << 4);
            CP_ASYNC16(ab + row * 128 + sw, A + (size_t)(bm + row) * lda + k0 + col * 4);
            CP_ASYNC16(bb + row * 128 + sw, B + (size_t)(bn + row) * ldb + k0 + col * 4);
        }
        CP_COMMIT();
    };

    uint32_t af[2][4][4], bf[2][8][2];
    auto ldfrag = [&](const float* As, const float* Bs, int ko, int fb) {
        const int cc0 = (((ko * 2)     ^ g4) << 2) | kl;
        const int cc1 = (((ko * 2 + 1) ^ g4) << 2) | kl;
        #pragma unroll
        for (int mt = 0; mt < 4; mt++) {
            int m = warpM + mt * 16 + g4;
            af[fb][mt][0] = __float_as_uint(As[m * 32 + cc0]);
            af[fb][mt][1] = __float_as_uint(As[(m + 8) * 32 + cc0]);
            af[fb][mt][2] = __float_as_uint(As[m * 32 + cc1]);
            af[fb][mt][3] = __float_as_uint(As[(m + 8) * 32 + cc1]);
        }
        #pragma unroll
        for (int nt = 0; nt < 8; nt++) {
            int n = warpN + nt * 8 + g4;
            bf[fb][nt][0] = __float_as_uint(Bs[n * 32 + cc0]);
            bf[fb][nt][1] = __float_as_uint(Bs[n * 32 + cc1]);
        }
    };
    auto domma = [&](int fb) {
        #pragma unroll
        for (int mt = 0; mt < 4; mt++)
            #pragma unroll
            for (int nt = 0; nt < 8; nt++)
                mma_tf32(acc[mt][nt], af[fb][mt][0], af[fb][mt][1],
                         af[fb][mt][2], af[fb][mt][3], bf[fb][nt][0], bf[fb][nt][1]);
    };

    auto compute = [&](int st) {
        const float* As = sm + st * 8192;
        const float* Bs = As + 4096;
        ldfrag(As, Bs, 0, 0);
        #pragma unroll
        for (int ko = 0; ko < 4; ko++) {
            if (ko < 3) ldfrag(As, Bs, ko + 1, (ko + 1) & 1);
            domma(ko & 1);
        }
    };

    const int nst = K / 32;
    issue(0, 0);
    if (nst > 1) issue(32, 1);
    int st = 0;
    for (int s = 0; s < nst; s++) {
        if (s + 1 < nst) { CP_WAIT(1); } else { CP_WAIT(0); }
        __syncthreads();
        if (s + 2 < nst) {
            int st2 = st + 2; if (st2 >= 3) st2 -= 3;
            issue((s + 2) * 32, st2);
        }
        compute(st);
        if (++st == 3) st = 0;
    }

    // ---- epilogue ----
    #pragma unroll
    for (int mt = 0; mt < 4; mt++) {
        #pragma unroll
        for (int rr = 0; rr < 2; rr++) {
            int r_ = bm + warpM + mt * 16 + g4 + rr * 8;
            float* Crow = C + (size_t)r_ * ldc;
            const float* Rrow = Rsd ? (Rsd + (size_t)r_ * ldr) : nullptr;
            #pragma unroll
            for (int nt = 0; nt < 8; nt++) {
                int col = bn + warpN + nt * 8 + kl * 2;
                float v0 = acc[mt][nt][rr * 2 + 0];
                float v1 = acc[mt][nt][rr * 2 + 1];
                if (bias) { v0 += bias[col]; v1 += bias[col + 1]; }
                if (ACT == 1) { v0 = gelu_tanh(v0); v1 = gelu_tanh(v1); }
                if (Rrow) { v0 += Rrow[col]; v1 += Rrow[col + 1]; }
                if (OUTR) { v0 = to_tf32(v0); v1 = to_tf32(v1); }
                *(float2*)(Crow + col) = make_float2(v0, v1);
            }
        }
    }
}

// ---------------- launch ----------------------------------------------------
extern "C" void kernel_launch(void* const* d_in, const int* in_sizes, int n_in,
                              void* d_out, int out_size) {
    const float* x      = (const float*)d_in[0];
    const float* mask   = (const float*)d_in[1];
    const float* cosp   = (const float*)d_in[2];
    const float* sinp   = (const float*)d_in[3];
    const float* qkv_w  = (const float*)d_in[4];
    const float* qkv_b  = (const float*)d_in[5];
    const float* proj_w = (const float*)d_in[6];
    const float* proj_b = (const float*)d_in[7];
    const float* fc1_w  = (const float*)d_in[8];
    const float* fc1_b  = (const float*)d_in[9];
    const float* fc2_w  = (const float*)d_in[10];
    const float* fc2_b  = (const float*)d_in[11];
    const float* ln1_g  = (const float*)d_in[12];
    const float* ln1_b  = (const float*)d_in[13];
    const float* ln2_g  = (const float*)d_in[14];
    const float* ln2_b  = (const float*)d_in[15];
    float* out = (float*)d_out;

    float *p_ln, *p_qkv, *p_ctx, *p_x1, *p_ffn;
    float *p_wqkv, *p_wproj, *p_wfc1, *p_wfc2;
    __nv_bfloat16 *p_qbf, *p_kbf, *p_vt;
    cudaGetSymbolAddress((void**)&p_ln,   g_ln);
    cudaGetSymbolAddress((void**)&p_qkv,  g_qkv);
    cudaGetSymbolAddress((void**)&p_ctx,  g_ctx);
    cudaGetSymbolAddress((void**)&p_x1,   g_x1);
    cudaGetSymbolAddress((void**)&p_ffn,  g_ffn);
    cudaGetSymbolAddress((void**)&p_wqkv, g_wqkv);
    cudaGetSymbolAddress((void**)&p_wproj,g_wproj);
    cudaGetSymbolAddress((void**)&p_wfc1, g_wfc1);
    cudaGetSymbolAddress((void**)&p_wfc2, g_wfc2);
    cudaGetSymbolAddress((void**)&p_qbf,  g_qbf);
    cudaGetSymbolAddress((void**)&p_kbf,  g_kbf);
    cudaGetSymbolAddress((void**)&p_vt,   g_vt);

    const int SMG = 3 * 8192 * 4;                          // 98304
    const int SMF = 2 * KB_BYTES + 2 * VB_BYTES;           // 88576
    cudaFuncSetAttribute(mma_gemm<0, 0>, cudaFuncAttributeMaxDynamicSharedMemorySize, SMG);
    cudaFuncSetAttribute(mma_gemm<0, 1>, cudaFuncAttributeMaxDynamicSharedMemorySize, SMG);
    cudaFuncSetAttribute(mma_gemm<1, 1>, cudaFuncAttributeMaxDynamicSharedMemorySize, SMG);
    cudaFuncSetAttribute(flash_kernel, cudaFuncAttributeMaxDynamicSharedMemorySize, SMF);

    // 0. round all weights to tf32 in one launch
    {
        int n0 = 3 * HH * HH / 4, n1 = HH * HH / 4;
        int n2 = IDIM * HH / 4,   n3 = HH * IDIM / 4;
        int mx = n2;
        round_all_kernel<<<dim3((mx + 255) / 256, 4), 256>>>(
            qkv_w, p_wqkv, n0, proj_w, p_wproj, n1,
            fc1_w, p_wfc1, n2, fc2_w, p_wfc2, n3);
    }

    // 1. LN1 (rounded output)
    ln_kernel<<<SS, 256>>>(x, ln1_g, ln1_b, p_ln);

    // 2. QKV = ln @ qkv_w^T + qkv_b  (rounded output)
    mma_gemm<0, 1><<<dim3(3840 / 128, SS / 128), 128, SMG>>>(
        p_ln, HH, p_wqkv, HH, p_qkv, 3 * HH,
        qkv_b, nullptr, 0, 3 * HH, HH);

    // 3. RoPE on q, k in place (rounded output)
    {
        int n = SS * NHEAD * (HDIM / 2);
        rope_kernel<<<(n + 255) / 256, 256>>>(p_qkv, cosp, sinp);
    }

    // 3b. bf16 conversions for attention
    {
        int n4 = SS * HH / 4;
        cvt_qk_kernel<<<dim3((n4 + 255) / 256, 2), 256>>>(p_qkv, p_qbf, p_kbf);
        cvt_vt_kernel<<<dim3(SS / 128, HDIM / 16, NHEAD), dim3(16, 16)>>>(p_qkv, p_vt);
    }

    // 4-6. fused flash attention (bf16) -> ctx (tf32-rounded output)
    flash_kernel<<<dim3(SS / 64, NHEAD), 128, SMF>>>(p_qbf, p_kbf, p_vt, mask, p_ctx);

    // 7. x1 = x + ctx @ proj_w^T + proj_b  (fp32: residual stream)
    mma_gemm<0, 0><<<dim3(HH / 128, SS / 128), 128, SMG>>>(
        p_ctx, HH, p_wproj, HH, p_x1, HH,
        proj_b, x, HH, HH, HH);

    // 8. LN2 (rounded output)
    ln_kernel<<<SS, 256>>>(p_x1, ln2_g, ln2_b, p_ln);

    // 9. ffn = gelu(ln @ fc1_w^T + fc1_b)  (rounded output)
    mma_gemm<1, 1><<<dim3(IDIM / 128, SS / 128), 128, SMG>>>(
        p_ln, HH, p_wfc1, HH, p_ffn, IDIM,
        fc1_b, nullptr, 0, IDIM, HH);

    // 10. out = x1 + ffn @ fc2_w^T + fc2_b  (fp32: final output)
    mma_gemm<0, 0><<<dim3(HH / 128, SS / 128), 128, SMG>>>(
        p_ffn, IDIM, p_wfc2, IDIM, out, HH,
        fc2_b, p_x1, HH, HH, IDIM);
}

// round 17
// speedup vs baseline: 1.5125x; 1.0987x over previous
#include <cuda_runtime.h>
#include <cuda_bf16.h>
#include <math.h>
#include <stdint.h>

#define SS 4096
#define HH 1280
#define NHEAD 16
#define HDIM 80
#define IDIM 5120
#define EPSV 1e-6f

// ---------------- scratch (static device memory; no allocs allowed) --------
__device__ float g_ln  [(size_t)SS * HH];            // LN2 out (tf32)
__device__ float g_qkv [(size_t)SS * 3 * HH];
__device__ float g_x1  [(size_t)SS * HH];
__device__ float g_ffn [(size_t)SS * IDIM];
// tf32-rounded weights (FFN)
__device__ float g_wfc1[(size_t)IDIM * HH];
__device__ float g_wfc2[(size_t)HH * IDIM];
// bf16 weights + activations (attention side)
__device__ __align__(16) __nv_bfloat16 g_wqkv_bf[(size_t)3 * HH * HH];
__device__ __align__(16) __nv_bfloat16 g_wproj_bf[(size_t)HH * HH];
__device__ __align__(16) __nv_bfloat16 g_ln_bf [(size_t)SS * HH];   // LN1 out
__device__ __align__(16) __nv_bfloat16 g_ctx_bf[(size_t)SS * HH];   // attn ctx
__device__ __align__(16) __nv_bfloat16 g_qbf[(size_t)SS * HH];
__device__ __align__(16) __nv_bfloat16 g_kbf[(size_t)SS * HH];
__device__ __align__(16) __nv_bfloat16 g_vt [(size_t)NHEAD * HDIM * SS]; // [h][hd][kv]

// ---------------- helpers ---------------------------------------------------
__device__ __forceinline__ float to_tf32(float x) {
    float r;
    asm("cvt.rna.tf32.f32 %0, %1;" : "=f"(r) : "f"(x));
    return r;
}
__device__ __forceinline__ float4 cvt4(float4 v) {
    v.x = to_tf32(v.x); v.y = to_tf32(v.y); v.z = to_tf32(v.z); v.w = to_tf32(v.w);
    return v;
}
__device__ __forceinline__ uint32_t smem_u32(const void* p) {
    uint32_t a;
    asm("{ .reg .u64 t; cvta.to.shared.u64 t, %1; cvt.u32.u64 %0, t; }" : "=r"(a) : "l"(p));
    return a;
}
__device__ __forceinline__ void mma_tf32(float* d, uint32_t a0, uint32_t a1,
                                         uint32_t a2, uint32_t a3,
                                         uint32_t b0, uint32_t b1) {
    asm volatile(
        "mma.sync.aligned.m16n8k8.row.col.f32.tf32.tf32.f32 "
        "{%0,%1,%2,%3}, {%4,%5,%6,%7}, {%8,%9}, {%0,%1,%2,%3};"
        : "+f"(d[0]), "+f"(d[1]), "+f"(d[2]), "+f"(d[3])
        : "r"(a0), "r"(a1), "r"(a2), "r"(a3), "r"(b0), "r"(b1));
}
__device__ __forceinline__ void mma_bf16(float* d, uint32_t a0, uint32_t a1,
                                         uint32_t a2, uint32_t a3,
                                         uint32_t b0, uint32_t b1) {
    asm volatile(
        "mma.sync.aligned.m16n8k16.row.col.f32.bf16.bf16.f32 "
        "{%0,%1,%2,%3}, {%4,%5,%6,%7}, {%8,%9}, {%0,%1,%2,%3};"
        : "+f"(d[0]), "+f"(d[1]), "+f"(d[2]), "+f"(d[3])
        : "r"(a0), "r"(a1), "r"(a2), "r"(a3), "r"(b0), "r"(b1));
}
__device__ __forceinline__ uint32_t packbf(float hi, float lo) {
    uint32_t r;
    asm("cvt.rn.bf16x2.f32 %0, %1, %2;" : "=r"(r) : "f"(hi), "f"(lo));
    return r;
}
#define CP_ASYNC16(dst, src) \
    asm volatile("cp.async.cg.shared.global [%0], [%1], 16;" :: "r"(dst), "l"(src) : "memory")
#define CP_COMMIT() asm volatile("cp.async.commit_group;" ::: "memory")
#define CP_WAIT(n)  asm volatile("cp.async.wait_group %0;" :: "n"(n) : "memory")

// ---------------- weight rounding / conversion (one launch) -----------------
// y=0: qkv_w -> bf16, y=1: proj_w -> bf16, y=2: fc1 -> tf32, y=3: fc2 -> tf32
__global__ void round_all_kernel(const float* s0, __nv_bfloat16* d0, int n0,
                                 const float* s1, __nv_bfloat16* d1, int n1,
                                 const float* s2, float* d2, int n2,
                                 const float* s3, float* d3, int n3) {
    int i = blockIdx.x * blockDim.x + threadIdx.x;
    int y = blockIdx.y;
    if (y == 0) {
        if (i < n0) {
            float4 v = ((const float4*)s0)[i];
            *(uint2*)(d0 + (size_t)i * 4) = make_uint2(packbf(v.y, v.x), packbf(v.w, v.z));
        }
    } else if (y == 1) {
        if (i < n1) {
            float4 v = ((const float4*)s1)[i];
            *(uint2*)(d1 + (size_t)i * 4) = make_uint2(packbf(v.y, v.x), packbf(v.w, v.z));
        }
    } else if (y == 2) {
        if (i < n2) ((float4*)d2)[i] = cvt4(((const float4*)s2)[i]);
    } else {
        if (i < n3) ((float4*)d3)[i] = cvt4(((const float4*)s3)[i]);
    }
}

// ---------------- bf16 conversions ------------------------------------------
__global__ void cvt_qk_kernel(const float* __restrict__ qkv,
                              __nv_bfloat16* __restrict__ qbf,
                              __nv_bfloat16* __restrict__ kbf) {
    int i = blockIdx.x * 256 + threadIdx.x;
    const int n4 = SS * HH / 4;
    if (i >= n4) return;
    int s = i / (HH / 4), c4 = i % (HH / 4);
    const float* src = qkv + (size_t)s * (3 * HH) + blockIdx.y * HH + c4 * 4;
    float4 v = *(const float4*)src;
    __nv_bfloat16* dst = (blockIdx.y ? kbf : qbf) + (size_t)s * HH + c4 * 4;
    *(uint2*)dst = make_uint2(packbf(v.y, v.x), packbf(v.w, v.z));
}
__global__ void cvt_vt_kernel(const float* __restrict__ qkv,
                              __nv_bfloat16* __restrict__ vt) {
    __shared__ float tile[16][129];
    int h = blockIdx.z, hd0 = blockIdx.y * 16, kv0 = blockIdx.x * 128;
    int tx = threadIdx.x, ty = threadIdx.y;
    #pragma unroll
    for (int j = 0; j < 8; j++) {
        int s = kv0 + ty + 16 * j;
        tile[tx][ty + 16 * j] = qkv[(size_t)s * (3 * HH) + 2 * HH + h * HDIM + hd0 + tx];
    }
    __syncthreads();
    #pragma unroll
    for (int j = 0; j < 8; j++) {
        int kv = tx + 16 * j;
        vt[((size_t)h * HDIM + hd0 + ty) * SS + kv0 + kv] = __float2bfloat16(tile[ty][kv]);
    }
}

// ---------------- reductions ----------------------------------------------
__device__ __forceinline__ float block_reduce_sum(float v) {
    __shared__ float sh_sum[32];
    int lane = threadIdx.x & 31, wid = threadIdx.x >> 5;
    #pragma unroll
    for (int o = 16; o; o >>= 1) v += __shfl_xor_sync(0xffffffffu, v, o);
    if (lane == 0) sh_sum[wid] = v;
    __syncthreads();
    v = (threadIdx.x < (blockDim.x >> 5)) ? sh_sum[threadIdx.x] : 0.f;
    if (wid == 0) {
        #pragma unroll
        for (int o = 16; o; o >>= 1) v += __shfl_xor_sync(0xffffffffu, v, o);
        if (lane == 0) sh_sum[0] = v;
    }
    __syncthreads();
    float r = sh_sum[0];
    __syncthreads();
    return r;
}

// ---------------- layernorm: fp32(tf32) and bf16 variants -------------------
__global__ void ln_kernel(const float* __restrict__ x, const float* __restrict__ g,
                          const float* __restrict__ b, float* __restrict__ out) {
    int row = blockIdx.x;
    const float* xr = x + (size_t)row * HH;
    float v[5]; float s = 0.f;
    #pragma unroll
    for (int i = 0; i < 5; i++) { v[i] = xr[threadIdx.x + i * 256]; s += v[i]; }
    float mean = block_reduce_sum(s) * (1.f / HH);
    float vs = 0.f;
    #pragma unroll
    for (int i = 0; i < 5; i++) { float d = v[i] - mean; vs += d * d; }
    float var = block_reduce_sum(vs) * (1.f / HH);
    float inv = rsqrtf(var + EPSV);
    float* o = out + (size_t)row * HH;
    #pragma unroll
    for (int i = 0; i < 5; i++) {
        int c = threadIdx.x + i * 256;
        o[c] = to_tf32((v[i] - mean) * inv * g[c] + b[c]);
    }
}
__global__ void ln_bf16_kernel(const float* __restrict__ x, const float* __restrict__ g,
                               const float* __restrict__ b, __nv_bfloat16* __restrict__ out) {
    int row = blockIdx.x;
    const float* xr = x + (size_t)row * HH;
    float v[5]; float s = 0.f;
    #pragma unroll
    for (int i = 0; i < 5; i++) { v[i] = xr[threadIdx.x + i * 256]; s += v[i]; }
    float mean = block_reduce_sum(s) * (1.f / HH);
    float vs = 0.f;
    #pragma unroll
    for (int i = 0; i < 5; i++) { float d = v[i] - mean; vs += d * d; }
    float var = block_reduce_sum(vs) * (1.f / HH);
    float inv = rsqrtf(var + EPSV);
    __nv_bfloat16* o = out + (size_t)row * HH;
    #pragma unroll
    for (int i = 0; i < 5; i++) {
        int c = threadIdx.x + i * 256;
        o[c] = __float2bfloat16((v[i] - mean) * inv * g[c] + b[c]);
    }
}

// ---------------- RoPE (fp32, in place) -------------------------------------
__global__ void rope_kernel(float* __restrict__ qkv, const float* __restrict__ cs,
                            const float* __restrict__ sn) {
    int idx = blockIdx.x * blockDim.x + threadIdx.x;
    if (idx >= SS * NHEAD * (HDIM / 2)) return;
    int d = idx % (HDIM / 2);
    int h = (idx / (HDIM / 2)) % NHEAD;
    int s = idx / ((HDIM / 2) * NHEAD);
    float c1 = cs[s * HDIM + d], c2 = cs[s * HDIM + d + 40];
    float s1 = sn[s * HDIM + d], s2 = sn[s * HDIM + d + 40];
    size_t base = (size_t)s * 3 * HH + h * HDIM;
    float* qp = qkv + base;
    float a = qp[d], bb = qp[d + 40];
    qp[d]      = a * c1 - bb * s1;
    qp[d + 40] = bb * c2 + a * s2;
    float* kp = qkv + base + HH;
    a = kp[d]; bb = kp[d + 40];
    kp[d]      = a * c1 - bb * s1;
    kp[d + 40] = bb * c2 + a * s2;
}

__device__ __forceinline__ float gelu_tanh(float x) {
    return 0.5f * x * (1.f + tanhf(0.7978845608028654f * (x + 0.044715f * x * x * x)));
}

// ================= flash attention v3 (bf16 m16n8k16) =======================
#define KR 88
#define VR 136
#define KB_BYTES (128 * KR * 2)   // 22528
#define VB_BYTES (HDIM * VR * 2)  // 21760
__global__ void __launch_bounds__(128)
flash_kernel(const __nv_bfloat16* __restrict__ qbf,
             const __nv_bfloat16* __restrict__ kbf,
             const __nv_bfloat16* __restrict__ vt,
             const float* __restrict__ mask, __nv_bfloat16* __restrict__ ctx) {
    extern __shared__ char fsm[];
    const uint32_t smb = smem_u32(fsm);

    const int tid  = threadIdx.x;
    const int wid  = tid >> 5;
    const int lane = tid & 31;
    const int g4   = lane >> 2;
    const int kl   = lane & 3;
    const int bm   = blockIdx.x * 64;
    const int h    = blockIdx.y;
    const float scale = rsqrtf((float)HDIM);

    auto issue = [&](int kv0, int b) {
        uint32_t kb = smb + b * KB_BYTES;
        uint32_t vb = smb + 2 * KB_BYTES + b * VB_BYTES;
        const __nv_bfloat16* ks = kbf + (size_t)kv0 * HH + h * HDIM;
        #pragma unroll
        for (int i = 0; i < 10; i++) {
            int c = i * 128 + tid;
            int row = c / 10, ch = c % 10;
            CP_ASYNC16(kb + (uint32_t)(row * (KR * 2) + ch * 16),
                       ks + (size_t)row * HH + ch * 8);
        }
        const __nv_bfloat16* vs = vt + (size_t)h * HDIM * SS + kv0;
        #pragma unroll
        for (int i = 0; i < 10; i++) {
            int c = i * 128 + tid;
            int row = c / 16, ch = c % 16;
            CP_ASYNC16(vb + (uint32_t)(row * (VR * 2) + ch * 16),
                       vs + (size_t)row * SS + ch * 8);
        }
        CP_COMMIT();
    };

    issue(0, 0);

    uint32_t qa[5][4];
    {
        int r0 = bm + wid * 16 + g4;
        const __nv_bfloat16* q0 = qbf + (size_t)r0 * HH + h * HDIM;
        const __nv_bfloat16* q1 = q0 + (size_t)8 * HH;
        #pragma unroll
        for (int ks = 0; ks < 5; ks++) {
            qa[ks][0] = *(const uint32_t*)(q0 + ks * 16 + 2 * kl);
            qa[ks][1] = *(const uint32_t*)(q1 + ks * 16 + 2 * kl);
            qa[ks][2] = *(const uint32_t*)(q0 + ks * 16 + 8 + 2 * kl);
            qa[ks][3] = *(const uint32_t*)(q1 + ks * 16 + 8 + 2 * kl);
        }
    }

    float Oa[10][4];
    #pragma unroll
    for (int i = 0; i < 10; i++)
        #pragma unroll
        for (int j = 0; j < 4; j++) Oa[i][j] = 0.f;
    float m0 = -INFINITY, m1 = -INFINITY, l0 = 0.f, l1 = 0.f;

    const float* mrow0 = mask + (size_t)(bm + wid * 16 + g4) * SS;
    const float* mrow1 = mrow0 + (size_t)8 * SS;

    constexpr int NT = SS / 128;
    for (int s = 0; s < NT; s++) {
        const int buf = s & 1;
        const int kv0 = s * 128;
        __syncthreads();
        if (s + 1 < NT) issue((s + 1) * 128, buf ^ 1);
        if (s + 1 < NT) { CP_WAIT(1); } else { CP_WAIT(0); }
        __syncthreads();

        const __nv_bfloat16* K_ = (const __nv_bfloat16*)(fsm + buf * KB_BYTES);
        const __nv_bfloat16* V_ = (const __nv_bfloat16*)(fsm + 2 * KB_BYTES + buf * VB_BYTES);

        float sa[16][4];
        #pragma unroll
        for (int nt = 0; nt < 16; nt++)
            #pragma unroll
            for (int j = 0; j < 4; j++) sa[nt][j] = 0.f;
        #pragma unroll
        for (int ks = 0; ks < 5; ks++) {
            #pragma unroll
            for (int nt = 0; nt < 16; nt++) {
                uint32_t b0 = *(const uint32_t*)(K_ + (nt * 8 + g4) * KR + ks * 16 + 2 * kl);
                uint32_t b1 = *(const uint32_t*)(K_ + (nt * 8 + g4) * KR + ks * 16 + 8 + 2 * kl);
                mma_bf16(sa[nt], qa[ks][0], qa[ks][1], qa[ks][2], qa[ks][3], b0, b1);
            }
        }

        float tmx0 = -INFINITY, tmx1 = -INFINITY;
        #pragma unroll
        for (int nt = 0; nt < 16; nt++) {
            float2 mk0 = *(const float2*)(mrow0 + kv0 + nt * 8 + 2 * kl);
            float2 mk1 = *(const float2*)(mrow1 + kv0 + nt * 8 + 2 * kl);
            sa[nt][0] = sa[nt][0] * scale + mk0.x;
            sa[nt][1] = sa[nt][1] * scale + mk0.y;
            sa[nt][2] = sa[nt][2] * scale + mk1.x;
            sa[nt][3] = sa[nt][3] * scale + mk1.y;
            tmx0 = fmaxf(tmx0, fmaxf(sa[nt][0], sa[nt][1]));
            tmx1 = fmaxf(tmx1, fmaxf(sa[nt][2], sa[nt][3]));
        }
        tmx0 = fmaxf(tmx0, __shfl_xor_sync(0xffffffffu, tmx0, 1));
        tmx0 = fmaxf(tmx0, __shfl_xor_sync(0xffffffffu, tmx0, 2));
        tmx1 = fmaxf(tmx1, __shfl_xor_sync(0xffffffffu, tmx1, 1));
        tmx1 = fmaxf(tmx1, __shfl_xor_sync(0xffffffffu, tmx1, 2));

        float nm0 = fmaxf(m0, tmx0), nm1 = fmaxf(m1, tmx1);
        float f0 = __expf(m0 - nm0), f1 = __expf(m1 - nm1);
        m0 = nm0; m1 = nm1;

        float ts0 = 0.f, ts1 = 0.f;
        #pragma unroll
        for (int nt = 0; nt < 16; nt++) {
            sa[nt][0] = __expf(sa[nt][0] - nm0);
            sa[nt][1] = __expf(sa[nt][1] - nm0);
            sa[nt][2] = __expf(sa[nt][2] - nm1);
            sa[nt][3] = __expf(sa[nt][3] - nm1);
            ts0 += sa[nt][0] + sa[nt][1];
            ts1 += sa[nt][2] + sa[nt][3];
        }
        ts0 += __shfl_xor_sync(0xffffffffu, ts0, 1);
        ts0 += __shfl_xor_sync(0xffffffffu, ts0, 2);
        ts1 += __shfl_xor_sync(0xffffffffu, ts1, 1);
        ts1 += __shfl_xor_sync(0xffffffffu, ts1, 2);
        l0 = l0 * f0 + ts0;
        l1 = l1 * f1 + ts1;

        #pragma unroll
        for (int no = 0; no < 10; no++) {
            Oa[no][0] *= f0; Oa[no][1] *= f0;
            Oa[no][2] *= f1; Oa[no][3] *= f1;
        }

        #pragma unroll
        for (int g = 0; g < 8; g++) {
            uint32_t A0 = packbf(sa[2 * g][1],     sa[2 * g][0]);
            uint32_t A1 = packbf(sa[2 * g][3],     sa[2 * g][2]);
            uint32_t A2 = packbf(sa[2 * g + 1][1], sa[2 * g + 1][0]);
            uint32_t A3 = packbf(sa[2 * g + 1][3], sa[2 * g + 1][2]);
            #pragma unroll
            for (int no = 0; no < 10; no++) {
                uint32_t b0 = *(const uint32_t*)(V_ + (no * 8 + g4) * VR + g * 16 + 2 * kl);
                uint32_t b1 = *(const uint32_t*)(V_ + (no * 8 + g4) * VR + g * 16 + 8 + 2 * kl);
                mma_bf16(Oa[no], A0, A1, A2, A3, b0, b1);
            }
        }
    }

    // ---- epilogue: O / l -> ctx (bf16: proj GEMM A operand) ----
    float i0 = 1.f / l0, i1 = 1.f / l1;
    int r0 = bm + wid * 16 + g4;
    __nv_bfloat16* c0p = ctx + (size_t)r0 * HH + h * HDIM;
    __nv_bfloat16* c1p = c0p + (size_t)8 * HH;
    #pragma unroll
    for (int no = 0; no < 10; no++) {
        *(uint32_t*)(c0p + no * 8 + 2 * kl) = packbf(Oa[no][1] * i0, Oa[no][0] * i0);
        *(uint32_t*)(c1p + no * 8 + 2 * kl) = packbf(Oa[no][3] * i1, Oa[no][2] * i1);
    }
}

// ================= TF32 GEMM v5: 3-stage cp.async + frag double-buffer ======
template<int ACT, int OUTR>
__global__ void __launch_bounds__(128)
mma_gemm(const float* __restrict__ A, int lda,
         const float* __restrict__ B, int ldb,
         float* __restrict__ C, int ldc,
         const float* __restrict__ bias,
         const float* __restrict__ Rsd, int ldr,
         int N, int K) {
    extern __shared__ float sm[];           // 3 stages x 8192 floats
    const uint32_t smb = smem_u32(sm);

    const int tid = threadIdx.x;
    const int wid = tid >> 5;
    const int lane = tid & 31;
    const int g4 = lane >> 2;
    const int kl = lane & 3;
    const int warpM = (wid >> 1) * 64;
    const int warpN = (wid & 1) * 64;
    const int bm = blockIdx.y * 128;
    const int bn = blockIdx.x * 128;

    float acc[4][8][4];
    #pragma unroll
    for (int i = 0; i < 4; i++)
        #pragma unroll
        for (int j = 0; j < 8; j++)
            #pragma unroll
            for (int q = 0; q < 4; q++) acc[i][j][q] = 0.f;

    auto issue = [&](int k0, int st) {
        uint32_t ab = smb + st * 32768;
        uint32_t bb = ab + 16384;
        #pragma unroll
        for (int i = 0; i < 8; i++) {
            int idx = i * 128 + tid;
            int row = idx >> 3, col = idx & 7;
            uint32_t sw = (uint32_t)((col ^ (row & 7)) << 4);
            CP_ASYNC16(ab + row * 128 + sw, A + (size_t)(bm + row) * lda + k0 + col * 4);
            CP_ASYNC16(bb + row * 128 + sw, B + (size_t)(bn + row) * ldb + k0 + col * 4);
        }
        CP_COMMIT();
    };

    uint32_t af[2][4][4], bf[2][8][2];
    auto ldfrag = [&](const float* As, const float* Bs, int ko, int fb) {
        const int cc0 = (((ko * 2)     ^ g4) << 2) | kl;
        const int cc1 = (((ko * 2 + 1) ^ g4) << 2) | kl;
        #pragma unroll
        for (int mt = 0; mt < 4; mt++) {
            int m = warpM + mt * 16 + g4;
            af[fb][mt][0] = __float_as_uint(As[m * 32 + cc0]);
            af[fb][mt][1] = __float_as_uint(As[(m + 8) * 32 + cc0]);
            af[fb][mt][2] = __float_as_uint(As[m * 32 + cc1]);
            af[fb][mt][3] = __float_as_uint(As[(m + 8) * 32 + cc1]);
        }
        #pragma unroll
        for (int nt = 0; nt < 8; nt++) {
            int n = warpN + nt * 8 + g4;
            bf[fb][nt][0] = __float_as_uint(Bs[n * 32 + cc0]);
            bf[fb][nt][1] = __float_as_uint(Bs[n * 32 + cc1]);
        }
    };
    auto domma = [&](int fb) {
        #pragma unroll
        for (int mt = 0; mt < 4; mt++)
            #pragma unroll
            for (int nt = 0; nt < 8; nt++)
                mma_tf32(acc[mt][nt], af[fb][mt][0], af[fb][mt][1],
                         af[fb][mt][2], af[fb][mt][3], bf[fb][nt][0], bf[fb][nt][1]);
    };

    auto compute = [&](int st) {
        const float* As = sm + st * 8192;
        const float* Bs = As + 4096;
        ldfrag(As, Bs, 0, 0);
        #pragma unroll
        for (int ko = 0; ko < 4; ko++) {
            if (ko < 3) ldfrag(As, Bs, ko + 1, (ko + 1) & 1);
            domma(ko & 1);
        }
    };

    const int nst = K / 32;
    issue(0, 0);
    if (nst > 1) issue(32, 1);
    int st = 0;
    for (int s = 0; s < nst; s++) {
        if (s + 1 < nst) { CP_WAIT(1); } else { CP_WAIT(0); }
        __syncthreads();
        if (s + 2 < nst) {
            int st2 = st + 2; if (st2 >= 3) st2 -= 3;
            issue((s + 2) * 32, st2);
        }
        compute(st);
        if (++st == 3) st = 0;
    }

    #pragma unroll
    for (int mt = 0; mt < 4; mt++) {
        #pragma unroll
        for (int rr = 0; rr < 2; rr++) {
            int r_ = bm + warpM + mt * 16 + g4 + rr * 8;
            float* Crow = C + (size_t)r_ * ldc;
            const float* Rrow = Rsd ? (Rsd + (size_t)r_ * ldr) : nullptr;
            #pragma unroll
            for (int nt = 0; nt < 8; nt++) {
                int col = bn + warpN + nt * 8 + kl * 2;
                float v0 = acc[mt][nt][rr * 2 + 0];
                float v1 = acc[mt][nt][rr * 2 + 1];
                if (bias) { v0 += bias[col]; v1 += bias[col + 1]; }
                if (ACT == 1) { v0 = gelu_tanh(v0); v1 = gelu_tanh(v1); }
                if (Rrow) { v0 += Rrow[col]; v1 += Rrow[col + 1]; }
                if (OUTR) { v0 = to_tf32(v0); v1 = to_tf32(v1); }
                *(float2*)(Crow + col) = make_float2(v0, v1);
            }
        }
    }
}

// ================= BF16 GEMM: 3-stage cp.async, BK=64, m16n8k16 =============
// A [M,K] bf16 row-major, B [N,K] bf16 row-major, C fp32 (+bias,+residual).
// Stage: 128 rows x 64 bf16 (128B/row) per operand, XOR-16B-chunk swizzle.
// Fragment mapping identical to (verified) flash bf16 kernel.
__global__ void __launch_bounds__(128)
gemm_bf(const __nv_bfloat16* __restrict__ A, int lda,
        const __nv_bfloat16* __restrict__ B, int ldb,
        float* __restrict__ C, int ldc,
        const float* __restrict__ bias,
        const float* __restrict__ Rsd, int ldr,
        int N, int K) {
    extern __shared__ char smc[];           // 3 stages x 32KB
    const uint32_t smb = smem_u32(smc);

    const int tid = threadIdx.x;
    const int wid = tid >> 5;
    const int lane = tid & 31;
    const int g4 = lane >> 2;
    const int kl = lane & 3;
    const int warpM = (wid >> 1) * 64;
    const int warpN = (wid & 1) * 64;
    const int bm = blockIdx.y * 128;
    const int bn = blockIdx.x * 128;

    float acc[4][8][4];
    #pragma unroll
    for (int i = 0; i < 4; i++)
        #pragma unroll
        for (int j = 0; j < 8; j++)
            #pragma unroll
            for (int q = 0; q < 4; q++) acc[i][j][q] = 0.f;

    auto issue = [&](int k0, int st) {
        uint32_t ab = smb + st * 32768;
        uint32_t bb = ab + 16384;
        #pragma unroll
        for (int i = 0; i < 8; i++) {
            int idx = i * 128 + tid;
            int row = idx >> 3, col = idx & 7;           // col: 16B chunk (8 bf16)
            uint32_t sw = (uint32_t)((col ^ (row & 7)) << 4);
            CP_ASYNC16(ab + row * 128 + sw, A + (size_t)(bm + row) * lda + k0 + col * 8);
            CP_ASYNC16(bb + row * 128 + sw, B + (size_t)(bn + row) * ldb + k0 + col * 8);
        }
        CP_COMMIT();
    };

    uint32_t af[2][4][4], bf[2][8][2];
    auto ldfrag = [&](const char* As, const char* Bs, int ko, int fb) {
        // k16 block ko: chunks 2ko (k 0..7) and 2ko+1 (k 8..15); lane offset 2kl bf16 = 4kl bytes
        #pragma unroll
        for (int mt = 0; mt < 4; mt++) {
            int m0 = warpM + mt * 16 + g4;
            int m1 = m0 + 8;
            af[fb][mt][0] = *(const uint32_t*)(As + m0 * 128 + (((2 * ko)     ^ (m0 & 7)) << 4) + kl * 4);
            af[fb][mt][1] = *(const uint32_t*)(As + m1 * 128 + (((2 * ko)     ^ (m1 & 7)) << 4) + kl * 4);
            af[fb][mt][2] = *(const uint32_t*)(As + m0 * 128 + (((2 * ko + 1) ^ (m0 & 7)) << 4) + kl * 4);
            af[fb][mt][3] = *(const uint32_t*)(As + m1 * 128 + (((2 * ko + 1) ^ (m1 & 7)) << 4) + kl * 4);
        }
        #pragma unroll
        for (int nt = 0; nt < 8; nt++) {
            int n = warpN + nt * 8 + g4;
            bf[fb][nt][0] = *(const uint32_t*)(Bs + n * 128 + (((2 * ko)     ^ (n & 7)) << 4) + kl * 4);
            bf[fb][nt][1] = *(const uint32_t*)(Bs + n * 128 + (((2 * ko + 1) ^ (n & 7)) << 4) + kl * 4);
        }
    };
    auto domma = [&](int fb) {
        #pragma unroll
        for (int mt = 0; mt < 4; mt++)
            #pragma unroll
            for (int nt = 0; nt < 8; nt++)
                mma_bf16(acc[mt][nt], af[fb][mt][0], af[fb][mt][1],
                         af[fb][mt][2], af[fb][mt][3], bf[fb][nt][0], bf[fb][nt][1]);
    };

    auto compute = [&](int st) {
        const char* As = smc + st * 32768;
        const char* Bs = As + 16384;
        ldfrag(As, Bs, 0, 0);
        #pragma unroll
        for (int ko = 0; ko < 4; ko++) {
            if (ko < 3) ldfrag(As, Bs, ko + 1, (ko + 1) & 1);
            domma(ko & 1);
        }
    };

    const int nst = K / 64;
    issue(0, 0);
    if (nst > 1) issue(64, 1);
    int st = 0;
    for (int s = 0; s < nst; s++) {
        if (s + 1 < nst) { CP_WAIT(1); } else { CP_WAIT(0); }
        __syncthreads();
        if (s + 2 < nst) {
            int st2 = st + 2; if (st2 >= 3) st2 -= 3;
            issue((s + 2) * 64, st2);
        }
        compute(st);
        if (++st == 3) st = 0;
    }

    #pragma unroll
    for (int mt = 0; mt < 4; mt++) {
        #pragma unroll
        for (int rr = 0; rr < 2; rr++) {
            int r_ = bm + warpM + mt * 16 + g4 + rr * 8;
            float* Crow = C + (size_t)r_ * ldc;
            const float* Rrow = Rsd ? (Rsd + (size_t)r_ * ldr) : nullptr;
            #pragma unroll
            for (int nt = 0; nt < 8; nt++) {
                int col = bn + warpN + nt * 8 + kl * 2;
                float v0 = acc[mt][nt][rr * 2 + 0];
                float v1 = acc[mt][nt][rr * 2 + 1];
                if (bias) { v0 += bias[col]; v1 += bias[col + 1]; }
                if (Rrow) { v0 += Rrow[col]; v1 += Rrow[col + 1]; }
                *(float2*)(Crow + col) = make_float2(v0, v1);
            }
        }
    }
}

// ---------------- launch ----------------------------------------------------
extern "C" void kernel_launch(void* const* d_in, const int* in_sizes, int n_in,
                              void* d_out, int out_size) {
    const float* x      = (const float*)d_in[0];
    const float* mask   = (const float*)d_in[1];
    const float* cosp   = (const float*)d_in[2];
    const float* sinp   = (const float*)d_in[3];
    const float* qkv_w  = (const float*)d_in[4];
    const float* qkv_b  = (const float*)d_in[5];
    const float* proj_w = (const float*)d_in[6];
    const float* proj_b = (const float*)d_in[7];
    const float* fc1_w  = (const float*)d_in[8];
    const float* fc1_b  = (const float*)d_in[9];
    const float* fc2_w  = (const float*)d_in[10];
    const float* fc2_b  = (const float*)d_in[11];
    const float* ln1_g  = (const float*)d_in[12];
    const float* ln1_b  = (const float*)d_in[13];
    const float* ln2_g  = (const float*)d_in[14];
    const float* ln2_b  = (const float*)d_in[15];
    float* out = (float*)d_out;

    float *p_ln, *p_qkv, *p_x1, *p_ffn, *p_wfc1, *p_wfc2;
    __nv_bfloat16 *p_wqkv_bf, *p_wproj_bf, *p_ln_bf, *p_ctx_bf, *p_qbf, *p_kbf, *p_vt;
    cudaGetSymbolAddress((void**)&p_ln,   g_ln);
    cudaGetSymbolAddress((void**)&p_qkv,  g_qkv);
    cudaGetSymbolAddress((void**)&p_x1,   g_x1);
    cudaGetSymbolAddress((void**)&p_ffn,  g_ffn);
    cudaGetSymbolAddress((void**)&p_wfc1, g_wfc1);
    cudaGetSymbolAddress((void**)&p_wfc2, g_wfc2);
    cudaGetSymbolAddress((void**)&p_wqkv_bf,  g_wqkv_bf);
    cudaGetSymbolAddress((void**)&p_wproj_bf, g_wproj_bf);
    cudaGetSymbolAddress((void**)&p_ln_bf,  g_ln_bf);
    cudaGetSymbolAddress((void**)&p_ctx_bf, g_ctx_bf);
    cudaGetSymbolAddress((void**)&p_qbf,  g_qbf);
    cudaGetSymbolAddress((void**)&p_kbf,  g_kbf);
    cudaGetSymbolAddress((void**)&p_vt,   g_vt);

    const int SMG = 3 * 8192 * 4;                          // 98304
    const int SMF = 2 * KB_BYTES + 2 * VB_BYTES;           // 88576
    cudaFuncSetAttribute(mma_gemm<0, 0>, cudaFuncAttributeMaxDynamicSharedMemorySize, SMG);
    cudaFuncSetAttribute(mma_gemm<1, 1>, cudaFuncAttributeMaxDynamicSharedMemorySize, SMG);
    cudaFuncSetAttribute(gemm_bf, cudaFuncAttributeMaxDynamicSharedMemorySize, SMG);
    cudaFuncSetAttribute(flash_kernel, cudaFuncAttributeMaxDynamicSharedMemorySize, SMF);

    // 0. weight conversions in one launch (bf16 for qkv/proj, tf32 for fc1/fc2)
    {
        int n0 = 3 * HH * HH / 4, n1 = HH * HH / 4;
        int n2 = IDIM * HH / 4,   n3 = HH * IDIM / 4;
        int mx = n2;
        round_all_kernel<<<dim3((mx + 255) / 256, 4), 256>>>(
            qkv_w, p_wqkv_bf, n0, proj_w, p_wproj_bf, n1,
            fc1_w, p_wfc1, n2, fc2_w, p_wfc2, n3);
    }

    // 1. LN1 -> bf16
    ln_bf16_kernel<<<SS, 256>>>(x, ln1_g, ln1_b, p_ln_bf);

    // 2. QKV = ln1 @ qkv_w^T + qkv_b  (bf16 GEMM, fp32 out)
    gemm_bf<<<dim3(3840 / 128, SS / 128), 128, SMG>>>(
        p_ln_bf, HH, p_wqkv_bf, HH, p_qkv, 3 * HH,
        qkv_b, nullptr, 0, 3 * HH, HH);

    // 3. RoPE on q, k in place
    {
        int n = SS * NHEAD * (HDIM / 2);
        rope_kernel<<<(n + 255) / 256, 256>>>(p_qkv, cosp, sinp);
    }

    // 3b. bf16 operand prep for attention
    {
        int n4 = SS * HH / 4;
        cvt_qk_kernel<<<dim3((n4 + 255) / 256, 2), 256>>>(p_qkv, p_qbf, p_kbf);
        cvt_vt_kernel<<<dim3(SS / 128, HDIM / 16, NHEAD), dim3(16, 16)>>>(p_qkv, p_vt);
    }

    // 4-6. fused flash attention (bf16) -> ctx bf16
    flash_kernel<<<dim3(SS / 64, NHEAD), 128, SMF>>>(p_qbf, p_kbf, p_vt, mask, p_ctx_bf);

    // 7. x1 = x + ctx @ proj_w^T + proj_b  (bf16 GEMM, fp32 residual out)
    gemm_bf<<<dim3(HH / 128, SS / 128), 128, SMG>>>(
        p_ctx_bf, HH, p_wproj_bf, HH, p_x1, HH,
        proj_b, x, HH, HH, HH);

    // 8. LN2 -> fp32 (tf32-rounded)
    ln_kernel<<<SS, 256>>>(p_x1, ln2_g, ln2_b, p_ln);

    // 9. ffn = gelu(ln2 @ fc1_w^T + fc1_b)  (tf32, rounded output)
    mma_gemm<1, 1><<<dim3(IDIM / 128, SS / 128), 128, SMG>>>(
        p_ln, HH, p_wfc1, HH, p_ffn, IDIM,
        fc1_b, nullptr, 0, IDIM, HH);

    // 10. out = x1 + ffn @ fc2_w^T + fc2_b  (tf32, fp32 final output)
    mma_gemm<0, 0><<<dim3(HH / 128, SS / 128), 128, SMG>>>(
        p_ffn, IDIM, p_wfc2, IDIM, out, HH,
        fc2_b, p_x1, HH, HH, IDIM);
}